// round 13
// baseline (speedup 1.0000x reference)
#include <cuda_runtime.h>
#include <cuda_fp16.h>
#include <cstdint>
#include <cstddef>

#define D0 32
#define D1 128
#define D2 64
#define NG 16
#define NEG_SLOPE 0.01f
#define EPSV 1e-5f
#define MAXN 1000000

// ---------------- scratch ----------------------------------------------------
__device__ __half g_h1h[(size_t)MAXN * D1];  // 256 MB fp16 pre-norm layer-1
__device__ __half g_h2h[(size_t)MAXN * D2];  // 128 MB fp16 pre-norm layer-2
__device__ __half g_w2ph[64 * 64 * 2];       // fp16 fragment-permuted W2 (16 KB)
__device__ float g_w1p[4 * 16 * 32 * 2];     // fragment-permuted tf32 W1
__device__ float g_sum1[NG * D1], g_sq1[NG * D1];
__device__ float g_sum2[NG * D2], g_sq2[NG * D2];
__device__ float g_scale1[NG * D1], g_shift1[NG * D1];
__device__ float g_scale2[NG * D2], g_shift2[NG * D2];
__device__ float g_cntf[NG];

__device__ __forceinline__ uint32_t f2tf32(float v) {
    uint32_t u;
    asm("cvt.rna.tf32.f32 %0, %1;" : "=r"(u) : "f"(v));
    return u;
}

// ---------------- init -------------------------------------------------------
__global__ void k_init(float* __restrict__ out, int out_n) {
    int i = blockIdx.x * blockDim.x + threadIdx.x;
    if (i < out_n) out[i] = __int_as_float(0xFF800000);
    if (i < NG * D1) { g_sum1[i] = 0.f; g_sq1[i] = 0.f; }
    if (i < NG * D2) { g_sum2[i] = 0.f; g_sq2[i] = 0.f; }
}

// ---------------- W2 -> fp16 m16n8k16 B-fragment layout ---------------------
__global__ void k_w2p(const float* __restrict__ W2) {
    const int i = blockIdx.x * blockDim.x + threadIdx.x;
    if (i >= D2 * D1) return;
    const int c = i >> 7;            // 0..63
    const int k = i & 127;           // 0..127
    const int kt = k >> 4;
    const int j = c >> 3;
    const int lane = ((c & 7) << 2) + ((k & 7) >> 1);
    const int reg = (k & 15) >> 3;
    const int off = (((kt * 8 + j) * 64 + lane * 2 + reg) << 1) + (k & 1);
    g_w2ph[off] = __float2half(W2[c * D1 + k]);
}

// ---------------- W1 -> tf32 m16n8k8 B-fragment layout ----------------------
__global__ void k_w1p(const float* __restrict__ W1) {
    const int i = blockIdx.x * blockDim.x + threadIdx.x;
    if (i >= D1 * D0) return;
    const int c = i >> 5;
    const int k = i & 31;
    const int kt = k >> 3, krow = k & 7;
    const int j = c >> 3, ncol = c & 7;
    const int off = ((kt * 16 + j) * 32 + ncol * 4 + (krow & 3)) * 2 + (krow >> 2);
    g_w1p[off] = __uint_as_float(f2tf32(W1[c * D0 + k]));
}

// ---------------- k1m: pure tf32 mma GEMM1 -> fp16 h1 -----------------------
#define M1BLK 64
#define FRS 132
#define A1_WORDS (16 * FRS)
#define B1_WORDS 4096

__global__ void __launch_bounds__(256) k1m(
    const float* __restrict__ x, const float* __restrict__ b1, int n)
{
    extern __shared__ float sm[];
    float* aperm = sm;
    float* bperm = aperm + A1_WORDS;
    float* b1s   = bperm + B1_WORDS;     // 128 floats

    const int t = threadIdx.x;
    const int base = blockIdx.x * M1BLK;
    const int cnt = min(M1BLK, n - base);
    const int w = t >> 5;
    const int lane = t & 31;

    {
        const float4* src = (const float4*)g_w1p;
        float4* dst = (float4*)bperm;
        for (int i = t; i < B1_WORDS / 4; i += 256) dst[i] = src[i];
        if (t < D1) b1s[t] = b1[t];
    }
    for (int i = t; i < M1BLK * 8; i += 256) {
        const int node = i >> 3;
        const int kq = (i & 7) << 2;
        float4 v;
        if (node < cnt) v = *(const float4*)(x + (size_t)(base + node) * D0 + kq);
        else { v.x = v.y = v.z = v.w = 0.f; }
        const int mt = node >> 4;
        const int kt = kq >> 3;
        const int rl = node & 15;
        const int regb = (rl >> 3) + (((kq & 7) >> 2) << 1);
        const int laneb = (rl & 7) << 2;
        float* fb = aperm + (mt * 4 + kt) * FRS;
        fb[(laneb + 0) * 4 + regb] = __uint_as_float(f2tf32(v.x));
        fb[(laneb + 1) * 4 + regb] = __uint_as_float(f2tf32(v.y));
        fb[(laneb + 2) * 4 + regb] = __uint_as_float(f2tf32(v.z));
        fb[(laneb + 3) * 4 + regb] = __uint_as_float(f2tf32(v.w));
    }
    __syncthreads();

    const int mt = w >> 1;
    const int nh = w & 1;

    float acc[8][4];
#pragma unroll
    for (int j = 0; j < 8; j++)
#pragma unroll
        for (int r = 0; r < 4; r++) acc[j][r] = 0.f;

#pragma unroll
    for (int kt = 0; kt < 4; kt++) {
        const float4 af = *(const float4*)(aperm + (mt * 4 + kt) * FRS + lane * 4);
        const uint32_t a0 = __float_as_uint(af.x), a1 = __float_as_uint(af.y);
        const uint32_t a2 = __float_as_uint(af.z), a3 = __float_as_uint(af.w);
#pragma unroll
        for (int j = 0; j < 8; j++) {
            const int jg = nh * 8 + j;
            const float2 bf = *(const float2*)(bperm + ((kt * 16 + jg) * 32 + lane) * 2);
            const uint32_t b0 = __float_as_uint(bf.x), b1r = __float_as_uint(bf.y);
            asm volatile(
                "mma.sync.aligned.m16n8k8.row.col.f32.tf32.tf32.f32 "
                "{%0,%1,%2,%3}, {%4,%5,%6,%7}, {%8,%9}, {%0,%1,%2,%3};"
                : "+f"(acc[j][0]), "+f"(acc[j][1]), "+f"(acc[j][2]), "+f"(acc[j][3])
                : "r"(a0), "r"(a1), "r"(a2), "r"(a3), "r"(b0), "r"(b1r));
        }
    }

    const int grp = lane >> 2, tig = lane & 3;
    const int l0 = mt * 16 + grp;
    const int l1 = l0 + 8;
#pragma unroll
    for (int j = 0; j < 8; j++) {
        const int nn = nh * 64 + j * 8 + tig * 2;
        const float bx = b1s[nn], by = b1s[nn + 1];
        const __half2 p0 = __floats2half2_rn(acc[j][0] + bx, acc[j][1] + by);
        const __half2 p1 = __floats2half2_rn(acc[j][2] + bx, acc[j][3] + by);
        if (l0 < cnt) *(__half2*)(g_h1h + (size_t)(base + l0) * D1 + nn) = p0;
        if (l1 < cnt) *(__half2*)(g_h1h + (size_t)(base + l1) * D1 + nn) = p1;
    }
}

// ---------------- k_stats1: vectorized per-graph sums from fp16 h1 ----------
__global__ void __launch_bounds__(256) k_stats1(const int* __restrict__ nidx, int n) {
    const int t = threadIdx.x;
    const int cg = (t & 15) << 3;
    const int nr = t >> 4;
    const int chunk = (n + gridDim.x - 1) / gridDim.x;
    const int start = blockIdx.x * chunk;
    const int end = min(start + chunk, n);

    float s[8], q[8];
#pragma unroll
    for (int u = 0; u < 8; u++) { s[u] = 0.f; q[u] = 0.f; }
    int curg = -1;

    for (int node = start + nr; node < end; node += 16) {
        const int g = __ldg(&nidx[node]);
        if (g != curg) {
            if (curg >= 0) {
#pragma unroll
                for (int u = 0; u < 8; u++) {
                    atomicAdd(&g_sum1[curg * D1 + cg + u], s[u]);
                    atomicAdd(&g_sq1[curg * D1 + cg + u], q[u]);
                    s[u] = 0.f; q[u] = 0.f;
                }
            }
            curg = g;
        }
        const float4 hv = *(const float4*)(g_h1h + (size_t)node * D1 + cg);
        const __half2* hp = (const __half2*)&hv;
#pragma unroll
        for (int p = 0; p < 4; p++) {
            const float2 f = __half22float2(hp[p]);
            s[2 * p + 0] += f.x; q[2 * p + 0] = fmaf(f.x, f.x, q[2 * p + 0]);
            s[2 * p + 1] += f.y; q[2 * p + 1] = fmaf(f.y, f.y, q[2 * p + 1]);
        }
    }
    if (curg >= 0) {
#pragma unroll
        for (int u = 0; u < 8; u++) {
            atomicAdd(&g_sum1[curg * D1 + cg + u], s[u]);
            atomicAdd(&g_sq1[curg * D1 + cg + u], q[u]);
        }
    }
}

// ---------------- k_stats2: vectorized per-graph sums from fp16 h2 ----------
__global__ void __launch_bounds__(256) k_stats2(const int* __restrict__ nidx, int n) {
    const int t = threadIdx.x;
    const int cg = (t & 7) << 3;       // 0..56
    const int nr = t >> 3;             // 0..31
    const int chunk = (n + gridDim.x - 1) / gridDim.x;
    const int start = blockIdx.x * chunk;
    const int end = min(start + chunk, n);

    float s[8], q[8];
#pragma unroll
    for (int u = 0; u < 8; u++) { s[u] = 0.f; q[u] = 0.f; }
    int curg = -1;

    for (int node = start + nr; node < end; node += 32) {
        const int g = __ldg(&nidx[node]);
        if (g != curg) {
            if (curg >= 0) {
#pragma unroll
                for (int u = 0; u < 8; u++) {
                    atomicAdd(&g_sum2[curg * D2 + cg + u], s[u]);
                    atomicAdd(&g_sq2[curg * D2 + cg + u], q[u]);
                    s[u] = 0.f; q[u] = 0.f;
                }
            }
            curg = g;
        }
        const float4 hv = *(const float4*)(g_h2h + (size_t)node * D2 + cg);
        const __half2* hp = (const __half2*)&hv;
#pragma unroll
        for (int p = 0; p < 4; p++) {
            const float2 f = __half22float2(hp[p]);
            s[2 * p + 0] += f.x; q[2 * p + 0] = fmaf(f.x, f.x, q[2 * p + 0]);
            s[2 * p + 1] += f.y; q[2 * p + 1] = fmaf(f.y, f.y, q[2 * p + 1]);
        }
    }
    if (curg >= 0) {
#pragma unroll
        for (int u = 0; u < 8; u++) {
            atomicAdd(&g_sum2[curg * D2 + cg + u], s[u]);
            atomicAdd(&g_sq2[curg * D2 + cg + u], q[u]);
        }
    }
}

// ---------------- finalize layer-1 norm -------------------------------------
__global__ void k_fin1(const int* __restrict__ nidx, int n,
                       const float* __restrict__ gamma, const float* __restrict__ beta)
{
    __shared__ int lb[NG + 1];
    const int t = threadIdx.x;
    if (t <= NG) {
        int lo = 0, hi = n;
        while (lo < hi) { int mid = (lo + hi) >> 1; if (nidx[mid] < t) lo = mid + 1; else hi = mid; }
        lb[t] = lo;
    }
    __syncthreads();
    if (t < NG) g_cntf[t] = (float)max(lb[t + 1] - lb[t], 1);
    for (int idx = t; idx < NG * D1; idx += blockDim.x) {
        const int g = idx >> 7, c = idx & 127;
        const float cf = (float)max(lb[g + 1] - lb[g], 1);
        const float mean = g_sum1[idx] / cf;
        const float var = fmaxf(g_sq1[idx] / cf - mean * mean, 0.f);
        const float sc = gamma[c] * rsqrtf(var + EPSV);
        g_scale1[idx] = sc;
        g_shift1[idx] = fmaf(-mean, sc, beta[c]);
    }
}

// ---------------- k3 fp16 mma: norm1+leaky -> f16 GEMM2 (pure) --------------
#define MBLK 128
#define A3_WORDS (64 * FRS)
#define B3_WORDS 4096

__global__ void __launch_bounds__(256) k3(
    const float* __restrict__ b2, const int* __restrict__ nidx, int n)
{
    extern __shared__ float sm[];
    float* aperm = sm;
    float* bperm = aperm + A3_WORDS;
    float* b2s   = bperm + B3_WORDS;           // 64 floats
    int*   gs    = (int*)(b2s + D2);           // 128 ints

    const int t = threadIdx.x;
    const int base = blockIdx.x * MBLK;
    const int cnt = min(MBLK, n - base);
    const int w = t >> 5;
    const int lane = t & 31;

    {   // stage fp16 B frags + bias
        const float4* src = (const float4*)g_w2ph;
        float4* dst = (float4*)bperm;
        for (int i = t; i < B3_WORDS / 4; i += 256) dst[i] = src[i];
        if (t < D2) b2s[t] = b2[t];
    }
    for (int i = t; i < MBLK; i += 256) gs[i] = (i < cnt) ? nidx[base + i] : nidx[base + cnt - 1];
    __syncthreads();

    // stage A: normalize+leaky h1 -> half2 fragment layout, full K=128
    for (int i = t; i < MBLK * 16; i += 256) {
        const int node = i >> 4;
        const int kq = (i & 15) << 3;
        float vv[8];
        if (node < cnt) {
            const float4 hv = *(const float4*)(g_h1h + (size_t)(base + node) * D1 + kq);
            const __half2* hp = (const __half2*)&hv;
            const int g = gs[node];
            const float* scp = g_scale1 + g * D1 + kq;
            const float* shp = g_shift1 + g * D1 + kq;
            const float4 sc0 = *(const float4*)(scp);
            const float4 sc1 = *(const float4*)(scp + 4);
            const float4 sh0 = *(const float4*)(shp);
            const float4 sh1 = *(const float4*)(shp + 4);
            float2 f0 = __half22float2(hp[0]);
            float2 f1 = __half22float2(hp[1]);
            float2 f2 = __half22float2(hp[2]);
            float2 f3 = __half22float2(hp[3]);
            vv[0] = fmaf(f0.x, sc0.x, sh0.x);
            vv[1] = fmaf(f0.y, sc0.y, sh0.y);
            vv[2] = fmaf(f1.x, sc0.z, sh0.z);
            vv[3] = fmaf(f1.y, sc0.w, sh0.w);
            vv[4] = fmaf(f2.x, sc1.x, sh1.x);
            vv[5] = fmaf(f2.y, sc1.y, sh1.y);
            vv[6] = fmaf(f3.x, sc1.z, sh1.z);
            vv[7] = fmaf(f3.y, sc1.w, sh1.w);
#pragma unroll
            for (int u = 0; u < 8; u++) vv[u] = vv[u] >= 0.f ? vv[u] : vv[u] * NEG_SLOPE;
        } else {
#pragma unroll
            for (int u = 0; u < 8; u++) vv[u] = 0.f;
        }
        const int mt = node >> 4;
        const int kt = kq >> 4;
        const int rl = node & 15;
        const int reg = (rl >> 3) + (((kq & 15) >> 3) << 1);
        float* fb = aperm + (mt * 8 + kt) * FRS;
        const int lb0 = (rl & 7) << 2;
#pragma unroll
        for (int p = 0; p < 4; p++) {
            const __half2 hv2 = __floats2half2_rn(vv[2 * p], vv[2 * p + 1]);
            fb[(lb0 + p) * 4 + reg] = __uint_as_float(*(const uint32_t*)&hv2);
        }
    }
    __syncthreads();

    float acc[8][4];
#pragma unroll
    for (int j = 0; j < 8; j++)
#pragma unroll
        for (int r = 0; r < 4; r++) acc[j][r] = 0.f;

#pragma unroll
    for (int kt = 0; kt < 8; kt++) {
        const float4 af = *(const float4*)(aperm + (w * 8 + kt) * FRS + lane * 4);
        const uint32_t a0 = __float_as_uint(af.x), a1 = __float_as_uint(af.y);
        const uint32_t a2 = __float_as_uint(af.z), a3 = __float_as_uint(af.w);
#pragma unroll
        for (int j = 0; j < 8; j++) {
            const float2 bf = *(const float2*)(bperm + ((kt * 8 + j) * 64 + lane * 2));
            const uint32_t b0 = __float_as_uint(bf.x), b1r = __float_as_uint(bf.y);
            asm volatile(
                "mma.sync.aligned.m16n8k16.row.col.f32.f16.f16.f32 "
                "{%0,%1,%2,%3}, {%4,%5,%6,%7}, {%8,%9}, {%0,%1,%2,%3};"
                : "+f"(acc[j][0]), "+f"(acc[j][1]), "+f"(acc[j][2]), "+f"(acc[j][3])
                : "r"(a0), "r"(a1), "r"(a2), "r"(a3), "r"(b0), "r"(b1r));
        }
    }

    // epilogue: bias + fp16 h2 store only
    const int grp = lane >> 2, tig = lane & 3;
    const int l0 = w * 16 + grp;
    const int l1 = l0 + 8;
#pragma unroll
    for (int j = 0; j < 8; j++) {
        const int nn = j * 8 + tig * 2;
        const float bx = b2s[nn], by = b2s[nn + 1];
        const __half2 p0 = __floats2half2_rn(acc[j][0] + bx, acc[j][1] + by);
        const __half2 p1 = __floats2half2_rn(acc[j][2] + bx, acc[j][3] + by);
        if (l0 < cnt) *(__half2*)(g_h2h + (size_t)(base + l0) * D2 + nn) = p0;
        if (l1 < cnt) *(__half2*)(g_h2h + (size_t)(base + l1) * D2 + nn) = p1;
    }
}

// ---------------- finalize layer-2 norm -------------------------------------
__global__ void k_fin2(const float* __restrict__ gamma, const float* __restrict__ beta) {
    const int t = threadIdx.x;
    for (int idx = t; idx < NG * D2; idx += blockDim.x) {
        const int g = idx >> 6, c = idx & 63;
        const float cf = g_cntf[g];
        const float mean = g_sum2[idx] / cf;
        const float var = fmaxf(g_sq2[idx] / cf - mean * mean, 0.f);
        const float sc = gamma[c] * rsqrtf(var + EPSV);
        g_scale2[idx] = sc;
        g_shift2[idx] = fmaf(-mean, sc, beta[c]);
    }
}

// ---------------- k5: 8 ch/thread, vectorized -------------------------------
__global__ void __launch_bounds__(256) k5(
    const int* __restrict__ nidx, const int* __restrict__ sidx,
    float* __restrict__ out, int n)
{
    const int idx = blockIdx.x * blockDim.x + threadIdx.x;
    if (idx >= n * 8) return;
    const int node = idx >> 3;
    const int cg = (idx & 7) << 3;
    const int g = __ldg(&nidx[node]);

    const float4 hv = *(const float4*)(g_h2h + (size_t)node * D2 + cg);
    const __half2* hp = (const __half2*)&hv;
    const float* scp = g_scale2 + g * D2 + cg;
    const float* shp = g_shift2 + g * D2 + cg;
    const float4 sc0 = *(const float4*)(scp);
    const float4 sc1 = *(const float4*)(scp + 4);
    const float4 sh0 = *(const float4*)(shp);
    const float4 sh1 = *(const float4*)(shp + 4);

    float v[8];
    {
        const float2 f0 = __half22float2(hp[0]);
        const float2 f1 = __half22float2(hp[1]);
        const float2 f2 = __half22float2(hp[2]);
        const float2 f3 = __half22float2(hp[3]);
        v[0] = fmaf(f0.x, sc0.x, sh0.x);
        v[1] = fmaf(f0.y, sc0.y, sh0.y);
        v[2] = fmaf(f1.x, sc0.z, sh0.z);
        v[3] = fmaf(f1.y, sc0.w, sh0.w);
        v[4] = fmaf(f2.x, sc1.x, sh1.x);
        v[5] = fmaf(f2.y, sc1.y, sh1.y);
        v[6] = fmaf(f3.x, sc1.z, sh1.z);
        v[7] = fmaf(f3.y, sc1.w, sh1.w);
#pragma unroll
        for (int u = 0; u < 8; u++) v[u] = v[u] >= 0.f ? v[u] : v[u] * NEG_SLOPE;
    }

    const int sp = __ldg(&sidx[node]);
    float* ap = out + (size_t)sp * D2 + cg;
    const float4 c0 = *(const float4*)ap;
    const float4 c1 = *(const float4*)(ap + 4);
    const float cur[8] = {c0.x, c0.y, c0.z, c0.w, c1.x, c1.y, c1.z, c1.w};
#pragma unroll
    for (int u = 0; u < 8; u++) {
        if (v[u] > cur[u]) {
            if (v[u] >= 0.f) atomicMax((int*)(ap + u), __float_as_int(v[u]));
            else             atomicMin((unsigned int*)(ap + u), __float_as_uint(v[u]));
        }
    }
}

// ---------------- k6: -inf -> 0 ---------------------------------------------
__global__ void k6(float* __restrict__ out, int out_n) {
    const int i = blockIdx.x * blockDim.x + threadIdx.x;
    if (i < out_n) {
        if (__float_as_uint(out[i]) == 0xFF800000u) out[i] = 0.f;
    }
}

// ---------------- launcher ---------------------------------------------------
extern "C" void kernel_launch(void* const* d_in, const int* in_sizes, int n_in,
                              void* d_out, int out_size)
{
    const float* x     = (const float*)d_in[0];
    const float* W1    = (const float*)d_in[1];
    const float* b1    = (const float*)d_in[2];
    const float* g1    = (const float*)d_in[3];
    const float* beta1 = (const float*)d_in[4];
    const float* W2    = (const float*)d_in[5];
    const float* b2    = (const float*)d_in[6];
    const float* g2    = (const float*)d_in[7];
    const float* beta2 = (const float*)d_in[8];
    const int*   nidx  = (const int*)d_in[9];
    const int*   sidx  = (const int*)d_in[10];
    float* out = (float*)d_out;

    const int n = in_sizes[0] / D0;
    const int smem_k3 = (A3_WORDS + B3_WORDS + D2) * 4 + MBLK * 4;
    const int smem_k1 = (A1_WORDS + B1_WORDS + D1) * 4;
    static int attr_set = 0;
    if (!attr_set) {
        cudaFuncSetAttribute(k3, cudaFuncAttributeMaxDynamicSharedMemorySize, smem_k3);
        cudaFuncSetAttribute(k1m, cudaFuncAttributeMaxDynamicSharedMemorySize, smem_k1);
        attr_set = 1;
    }

    k_init<<<(out_size + 255) / 256, 256>>>(out, out_size);
    k_w2p<<<(D1 * D2 + 255) / 256, 256>>>(W2);
    k_w1p<<<(D1 * D0 + 255) / 256, 256>>>(W1);
    k1m<<<(n + M1BLK - 1) / M1BLK, 256, smem_k1>>>(x, b1, n);
    k_stats1<<<512, 256>>>(nidx, n);
    k_fin1<<<1, 1024>>>(nidx, n, g1, beta1);
    k3<<<(n + MBLK - 1) / MBLK, 256, smem_k3>>>(b2, nidx, n);
    k_stats2<<<512, 256>>>(nidx, n);
    k_fin2<<<1, 1024>>>(g2, beta2);
    k5<<<(n * 8 + 255) / 256, 256>>>(nidx, sidx, out, n);
    k6<<<(out_size + 255) / 256, 256>>>(out, out_size);
}

// round 14
// speedup vs baseline: 1.0848x; 1.0848x over previous
#include <cuda_runtime.h>
#include <cuda_fp16.h>
#include <cstdint>
#include <cstddef>

#define D0 32
#define D1 128
#define D2 64
#define NG 16
#define NEG_SLOPE 0.01f
#define EPSV 1e-5f
#define MAXN 1000000

// ---------------- scratch ----------------------------------------------------
__device__ __half g_h1h[(size_t)MAXN * D1];  // 256 MB fp16 pre-norm layer-1
__device__ __half g_h2h[(size_t)MAXN * D2];  // 128 MB fp16 pre-norm layer-2
__device__ __half g_w2ph[64 * 64 * 2];       // fp16 fragment-permuted W2 (16 KB)
__device__ float g_w1p[4 * 16 * 32 * 2];     // fragment-permuted tf32 W1
__device__ float g_sum1[NG * D1], g_sq1[NG * D1];
__device__ float g_sum2[NG * D2], g_sq2[NG * D2];
__device__ float g_scale1[NG * D1], g_shift1[NG * D1];
__device__ float g_scale2[NG * D2], g_shift2[NG * D2];
__device__ float g_cntf[NG];

__device__ __forceinline__ uint32_t f2tf32(float v) {
    uint32_t u;
    asm("cvt.rna.tf32.f32 %0, %1;" : "=r"(u) : "f"(v));
    return u;
}

// ---------------- init -------------------------------------------------------
__global__ void k_init(float* __restrict__ out, int out_n) {
    int i = blockIdx.x * blockDim.x + threadIdx.x;
    if (i < out_n) out[i] = __int_as_float(0xFF800000);
    if (i < NG * D1) { g_sum1[i] = 0.f; g_sq1[i] = 0.f; }
    if (i < NG * D2) { g_sum2[i] = 0.f; g_sq2[i] = 0.f; }
}

// ---------------- W2 -> fp16 m16n8k16 B-fragment layout ---------------------
__global__ void k_w2p(const float* __restrict__ W2) {
    const int i = blockIdx.x * blockDim.x + threadIdx.x;
    if (i >= D2 * D1) return;
    const int c = i >> 7;
    const int k = i & 127;
    const int kt = k >> 4;
    const int j = c >> 3;
    const int lane = ((c & 7) << 2) + ((k & 7) >> 1);
    const int reg = (k & 15) >> 3;
    const int off = (((kt * 8 + j) * 64 + lane * 2 + reg) << 1) + (k & 1);
    g_w2ph[off] = __float2half(W2[c * D1 + k]);
}

// ---------------- W1 -> tf32 m16n8k8 B-fragment layout ----------------------
__global__ void k_w1p(const float* __restrict__ W1) {
    const int i = blockIdx.x * blockDim.x + threadIdx.x;
    if (i >= D1 * D0) return;
    const int c = i >> 5;
    const int k = i & 31;
    const int kt = k >> 3, krow = k & 7;
    const int j = c >> 3, ncol = c & 7;
    const int off = ((kt * 16 + j) * 32 + ncol * 4 + (krow & 3)) * 2 + (krow >> 2);
    g_w1p[off] = __uint_as_float(f2tf32(W1[c * D0 + k]));
}

// ---------------- k1m: pure tf32 mma GEMM1 -> fp16 h1 -----------------------
#define M1BLK 64
#define FRS 132
#define A1_WORDS (16 * FRS)
#define B1_WORDS 4096

__global__ void __launch_bounds__(256) k1m(
    const float* __restrict__ x, const float* __restrict__ b1, int n)
{
    extern __shared__ float sm[];
    float* aperm = sm;
    float* bperm = aperm + A1_WORDS;
    float* b1s   = bperm + B1_WORDS;     // 128 floats

    const int t = threadIdx.x;
    const int base = blockIdx.x * M1BLK;
    const int cnt = min(M1BLK, n - base);
    const int w = t >> 5;
    const int lane = t & 31;

    {
        const float4* src = (const float4*)g_w1p;
        float4* dst = (float4*)bperm;
        for (int i = t; i < B1_WORDS / 4; i += 256) dst[i] = src[i];
        if (t < D1) b1s[t] = b1[t];
    }
    for (int i = t; i < M1BLK * 8; i += 256) {
        const int node = i >> 3;
        const int kq = (i & 7) << 2;
        float4 v;
        if (node < cnt) v = *(const float4*)(x + (size_t)(base + node) * D0 + kq);
        else { v.x = v.y = v.z = v.w = 0.f; }
        const int mt = node >> 4;
        const int kt = kq >> 3;
        const int rl = node & 15;
        const int regb = (rl >> 3) + (((kq & 7) >> 2) << 1);
        const int laneb = (rl & 7) << 2;
        float* fb = aperm + (mt * 4 + kt) * FRS;
        fb[(laneb + 0) * 4 + regb] = __uint_as_float(f2tf32(v.x));
        fb[(laneb + 1) * 4 + regb] = __uint_as_float(f2tf32(v.y));
        fb[(laneb + 2) * 4 + regb] = __uint_as_float(f2tf32(v.z));
        fb[(laneb + 3) * 4 + regb] = __uint_as_float(f2tf32(v.w));
    }
    __syncthreads();

    const int mt = w >> 1;
    const int nh = w & 1;

    float acc[8][4];
#pragma unroll
    for (int j = 0; j < 8; j++)
#pragma unroll
        for (int r = 0; r < 4; r++) acc[j][r] = 0.f;

#pragma unroll
    for (int kt = 0; kt < 4; kt++) {
        const float4 af = *(const float4*)(aperm + (mt * 4 + kt) * FRS + lane * 4);
        const uint32_t a0 = __float_as_uint(af.x), a1 = __float_as_uint(af.y);
        const uint32_t a2 = __float_as_uint(af.z), a3 = __float_as_uint(af.w);
#pragma unroll
        for (int j = 0; j < 8; j++) {
            const int jg = nh * 8 + j;
            const float2 bf = *(const float2*)(bperm + ((kt * 16 + jg) * 32 + lane) * 2);
            const uint32_t b0 = __float_as_uint(bf.x), b1r = __float_as_uint(bf.y);
            asm volatile(
                "mma.sync.aligned.m16n8k8.row.col.f32.tf32.tf32.f32 "
                "{%0,%1,%2,%3}, {%4,%5,%6,%7}, {%8,%9}, {%0,%1,%2,%3};"
                : "+f"(acc[j][0]), "+f"(acc[j][1]), "+f"(acc[j][2]), "+f"(acc[j][3])
                : "r"(a0), "r"(a1), "r"(a2), "r"(a3), "r"(b0), "r"(b1r));
        }
    }

    const int grp = lane >> 2, tig = lane & 3;
    const int l0 = mt * 16 + grp;
    const int l1 = l0 + 8;
#pragma unroll
    for (int j = 0; j < 8; j++) {
        const int nn = nh * 64 + j * 8 + tig * 2;
        const float bx = b1s[nn], by = b1s[nn + 1];
        const __half2 p0 = __floats2half2_rn(acc[j][0] + bx, acc[j][1] + by);
        const __half2 p1 = __floats2half2_rn(acc[j][2] + bx, acc[j][3] + by);
        if (l0 < cnt) *(__half2*)(g_h1h + (size_t)(base + l0) * D1 + nn) = p0;
        if (l1 < cnt) *(__half2*)(g_h1h + (size_t)(base + l1) * D1 + nn) = p1;
    }
}

// ---------------- k_stats1: vectorized per-graph sums from fp16 h1 ----------
__global__ void __launch_bounds__(256) k_stats1(const int* __restrict__ nidx, int n) {
    const int t = threadIdx.x;
    const int cg = (t & 15) << 3;
    const int nr = t >> 4;
    const int chunk = (n + gridDim.x - 1) / gridDim.x;
    const int start = blockIdx.x * chunk;
    const int end = min(start + chunk, n);

    float s[8], q[8];
#pragma unroll
    for (int u = 0; u < 8; u++) { s[u] = 0.f; q[u] = 0.f; }
    int curg = -1;

    for (int node = start + nr; node < end; node += 16) {
        const int g = __ldg(&nidx[node]);
        if (g != curg) {
            if (curg >= 0) {
#pragma unroll
                for (int u = 0; u < 8; u++) {
                    atomicAdd(&g_sum1[curg * D1 + cg + u], s[u]);
                    atomicAdd(&g_sq1[curg * D1 + cg + u], q[u]);
                    s[u] = 0.f; q[u] = 0.f;
                }
            }
            curg = g;
        }
        const float4 hv = *(const float4*)(g_h1h + (size_t)node * D1 + cg);
        const __half2* hp = (const __half2*)&hv;
#pragma unroll
        for (int p = 0; p < 4; p++) {
            const float2 f = __half22float2(hp[p]);
            s[2 * p + 0] += f.x; q[2 * p + 0] = fmaf(f.x, f.x, q[2 * p + 0]);
            s[2 * p + 1] += f.y; q[2 * p + 1] = fmaf(f.y, f.y, q[2 * p + 1]);
        }
    }
    if (curg >= 0) {
#pragma unroll
        for (int u = 0; u < 8; u++) {
            atomicAdd(&g_sum1[curg * D1 + cg + u], s[u]);
            atomicAdd(&g_sq1[curg * D1 + cg + u], q[u]);
        }
    }
}

// ---------------- finalize layer-1 norm -------------------------------------
__global__ void k_fin1(const int* __restrict__ nidx, int n,
                       const float* __restrict__ gamma, const float* __restrict__ beta)
{
    __shared__ int lb[NG + 1];
    const int t = threadIdx.x;
    if (t <= NG) {
        int lo = 0, hi = n;
        while (lo < hi) { int mid = (lo + hi) >> 1; if (nidx[mid] < t) lo = mid + 1; else hi = mid; }
        lb[t] = lo;
    }
    __syncthreads();
    if (t < NG) g_cntf[t] = (float)max(lb[t + 1] - lb[t], 1);
    for (int idx = t; idx < NG * D1; idx += blockDim.x) {
        const int g = idx >> 7, c = idx & 127;
        const float cf = (float)max(lb[g + 1] - lb[g], 1);
        const float mean = g_sum1[idx] / cf;
        const float var = fmaxf(g_sq1[idx] / cf - mean * mean, 0.f);
        const float sc = gamma[c] * rsqrtf(var + EPSV);
        g_scale1[idx] = sc;
        g_shift1[idx] = fmaf(-mean, sc, beta[c]);
    }
}

// ---------------- k3 fp16 mma: norm1+leaky -> f16 GEMM2 + fused stats2 ------
#define MBLK 128
#define SRG 4
#define A3_WORDS (64 * FRS)
#define B3_WORDS 4096

__global__ void __launch_bounds__(256) k3(
    const float* __restrict__ b2, const int* __restrict__ nidx, int n)
{
    extern __shared__ float sm[];
    float* aperm = sm;
    float* bperm = aperm + A3_WORDS;
    float* sred  = bperm + B3_WORDS;
    float* b2s   = sred + SRG * D2 * 2;
    int*   gs    = (int*)(b2s + D2);

    const int t = threadIdx.x;
    const int base = blockIdx.x * MBLK;
    const int cnt = min(MBLK, n - base);
    const int w = t >> 5;
    const int lane = t & 31;

    {   // stage fp16 B frags + bias
        const float4* src = (const float4*)g_w2ph;
        float4* dst = (float4*)bperm;
        for (int i = t; i < B3_WORDS / 4; i += 256) dst[i] = src[i];
        if (t < D2) b2s[t] = b2[t];
    }
    for (int i = t; i < SRG * D2 * 2; i += 256) sred[i] = 0.f;
    for (int i = t; i < MBLK; i += 256) gs[i] = (i < cnt) ? nidx[base + i] : nidx[base + cnt - 1];
    __syncthreads();
    const int gmin = gs[0];

    // stage A: normalize+leaky h1 -> half2 fragment layout, full K=128
    for (int i = t; i < MBLK * 16; i += 256) {
        const int node = i >> 4;
        const int kq = (i & 15) << 3;
        float vv[8];
        if (node < cnt) {
            const float4 hv = *(const float4*)(g_h1h + (size_t)(base + node) * D1 + kq);
            const __half2* hp = (const __half2*)&hv;
            const int g = gs[node];
            const float* scp = g_scale1 + g * D1 + kq;
            const float* shp = g_shift1 + g * D1 + kq;
            const float4 sc0 = *(const float4*)(scp);
            const float4 sc1 = *(const float4*)(scp + 4);
            const float4 sh0 = *(const float4*)(shp);
            const float4 sh1 = *(const float4*)(shp + 4);
            float2 f0 = __half22float2(hp[0]);
            float2 f1 = __half22float2(hp[1]);
            float2 f2 = __half22float2(hp[2]);
            float2 f3 = __half22float2(hp[3]);
            vv[0] = fmaf(f0.x, sc0.x, sh0.x);
            vv[1] = fmaf(f0.y, sc0.y, sh0.y);
            vv[2] = fmaf(f1.x, sc0.z, sh0.z);
            vv[3] = fmaf(f1.y, sc0.w, sh0.w);
            vv[4] = fmaf(f2.x, sc1.x, sh1.x);
            vv[5] = fmaf(f2.y, sc1.y, sh1.y);
            vv[6] = fmaf(f3.x, sc1.z, sh1.z);
            vv[7] = fmaf(f3.y, sc1.w, sh1.w);
#pragma unroll
            for (int u = 0; u < 8; u++) vv[u] = vv[u] >= 0.f ? vv[u] : vv[u] * NEG_SLOPE;
        } else {
#pragma unroll
            for (int u = 0; u < 8; u++) vv[u] = 0.f;
        }
        const int mt = node >> 4;
        const int kt = kq >> 4;
        const int rl = node & 15;
        const int reg = (rl >> 3) + (((kq & 15) >> 3) << 1);
        float* fb = aperm + (mt * 8 + kt) * FRS;
        const int lb0 = (rl & 7) << 2;
#pragma unroll
        for (int p = 0; p < 4; p++) {
            const __half2 hv2 = __floats2half2_rn(vv[2 * p], vv[2 * p + 1]);
            fb[(lb0 + p) * 4 + reg] = __uint_as_float(*(const uint32_t*)&hv2);
        }
    }
    __syncthreads();

    float acc[8][4];
#pragma unroll
    for (int j = 0; j < 8; j++)
#pragma unroll
        for (int r = 0; r < 4; r++) acc[j][r] = 0.f;

#pragma unroll
    for (int kt = 0; kt < 8; kt++) {
        const float4 af = *(const float4*)(aperm + (w * 8 + kt) * FRS + lane * 4);
        const uint32_t a0 = __float_as_uint(af.x), a1 = __float_as_uint(af.y);
        const uint32_t a2 = __float_as_uint(af.z), a3 = __float_as_uint(af.w);
#pragma unroll
        for (int j = 0; j < 8; j++) {
            const float2 bf = *(const float2*)(bperm + ((kt * 8 + j) * 64 + lane * 2));
            const uint32_t b0 = __float_as_uint(bf.x), b1r = __float_as_uint(bf.y);
            asm volatile(
                "mma.sync.aligned.m16n8k16.row.col.f32.f16.f16.f32 "
                "{%0,%1,%2,%3}, {%4,%5,%6,%7}, {%8,%9}, {%0,%1,%2,%3};"
                : "+f"(acc[j][0]), "+f"(acc[j][1]), "+f"(acc[j][2]), "+f"(acc[j][3])
                : "r"(a0), "r"(a1), "r"(a2), "r"(a3), "r"(b0), "r"(b1r));
        }
    }

    // epilogue: bias, fp16 h2 store, fused stats on rounded values
    const int grp = lane >> 2, tig = lane & 3;
    const int l0 = w * 16 + grp;
    const int l1 = l0 + 8;
    const bool uniform = (w * 16 + 15 < cnt) && (gs[w * 16] == gs[w * 16 + 15]);

#pragma unroll
    for (int j = 0; j < 8; j++) {
        const int nn = j * 8 + tig * 2;
        const float bx = b2s[nn], by = b2s[nn + 1];
        const __half2 p0 = __floats2half2_rn(acc[j][0] + bx, acc[j][1] + by);
        const __half2 p1 = __floats2half2_rn(acc[j][2] + bx, acc[j][3] + by);
        const float2 r0 = __half22float2(p0);
        const float2 r1 = __half22float2(p1);
        if (l0 < cnt) *(__half2*)(g_h2h + (size_t)(base + l0) * D2 + nn) = p0;
        if (l1 < cnt) *(__half2*)(g_h2h + (size_t)(base + l1) * D2 + nn) = p1;

        if (uniform) {
            float s0 = r0.x + r1.x, s1 = r0.y + r1.y;
            float q0 = r0.x * r0.x + r1.x * r1.x, q1 = r0.y * r0.y + r1.y * r1.y;
#pragma unroll
            for (int off = 4; off < 32; off <<= 1) {
                s0 += __shfl_xor_sync(0xffffffffu, s0, off);
                s1 += __shfl_xor_sync(0xffffffffu, s1, off);
                q0 += __shfl_xor_sync(0xffffffffu, q0, off);
                q1 += __shfl_xor_sync(0xffffffffu, q1, off);
            }
            if (lane < 4) {
                const int gl = gs[w * 16] - gmin;
                atomicAdd(&sred[(gl * D2 + nn) * 2 + 0], s0);
                atomicAdd(&sred[(gl * D2 + nn) * 2 + 1], q0);
                atomicAdd(&sred[(gl * D2 + nn + 1) * 2 + 0], s1);
                atomicAdd(&sred[(gl * D2 + nn + 1) * 2 + 1], q1);
            }
        } else {
            if (l0 < cnt) {
                const int gl = gs[l0] - gmin;
                if (gl < SRG) {
                    atomicAdd(&sred[(gl * D2 + nn) * 2 + 0], r0.x);
                    atomicAdd(&sred[(gl * D2 + nn) * 2 + 1], r0.x * r0.x);
                    atomicAdd(&sred[(gl * D2 + nn + 1) * 2 + 0], r0.y);
                    atomicAdd(&sred[(gl * D2 + nn + 1) * 2 + 1], r0.y * r0.y);
                } else {
                    const int g = gs[l0];
                    atomicAdd(&g_sum2[g * D2 + nn], r0.x);
                    atomicAdd(&g_sq2[g * D2 + nn], r0.x * r0.x);
                    atomicAdd(&g_sum2[g * D2 + nn + 1], r0.y);
                    atomicAdd(&g_sq2[g * D2 + nn + 1], r0.y * r0.y);
                }
            }
            if (l1 < cnt) {
                const int gl = gs[l1] - gmin;
                if (gl < SRG) {
                    atomicAdd(&sred[(gl * D2 + nn) * 2 + 0], r1.x);
                    atomicAdd(&sred[(gl * D2 + nn) * 2 + 1], r1.x * r1.x);
                    atomicAdd(&sred[(gl * D2 + nn + 1) * 2 + 0], r1.y);
                    atomicAdd(&sred[(gl * D2 + nn + 1) * 2 + 1], r1.y * r1.y);
                } else {
                    const int g = gs[l1];
                    atomicAdd(&g_sum2[g * D2 + nn], r1.x);
                    atomicAdd(&g_sq2[g * D2 + nn], r1.x * r1.x);
                    atomicAdd(&g_sum2[g * D2 + nn + 1], r1.y);
                    atomicAdd(&g_sq2[g * D2 + nn + 1], r1.y * r1.y);
                }
            }
        }
    }
    __syncthreads();

    const int span = min(gs[cnt - 1] - gmin + 1, SRG);
    for (int ii = t; ii < span * D2; ii += 256) {
        const int gl = ii / D2;
        const int c = ii % D2;
        const float sv = sred[(gl * D2 + c) * 2 + 0];
        const float qv = sred[(gl * D2 + c) * 2 + 1];
        if (sv != 0.f || qv != 0.f) {
            atomicAdd(&g_sum2[(gmin + gl) * D2 + c], sv);
            atomicAdd(&g_sq2[(gmin + gl) * D2 + c], qv);
        }
    }
}

// ---------------- finalize layer-2 norm -------------------------------------
__global__ void k_fin2(const float* __restrict__ gamma, const float* __restrict__ beta) {
    const int t = threadIdx.x;
    for (int idx = t; idx < NG * D2; idx += blockDim.x) {
        const int g = idx >> 6, c = idx & 63;
        const float cf = g_cntf[g];
        const float mean = g_sum2[idx] / cf;
        const float var = fmaxf(g_sq2[idx] / cf - mean * mean, 0.f);
        const float sc = gamma[c] * rsqrtf(var + EPSV);
        g_scale2[idx] = sc;
        g_shift2[idx] = fmaf(-mean, sc, beta[c]);
    }
}

// ---------------- k5: 8 ch/thread, vectorized -------------------------------
__global__ void __launch_bounds__(256) k5(
    const int* __restrict__ nidx, const int* __restrict__ sidx,
    float* __restrict__ out, int n)
{
    const int idx = blockIdx.x * blockDim.x + threadIdx.x;
    if (idx >= n * 8) return;
    const int node = idx >> 3;
    const int cg = (idx & 7) << 3;
    const int g = __ldg(&nidx[node]);

    const float4 hv = *(const float4*)(g_h2h + (size_t)node * D2 + cg);
    const __half2* hp = (const __half2*)&hv;
    const float* scp = g_scale2 + g * D2 + cg;
    const float* shp = g_shift2 + g * D2 + cg;
    const float4 sc0 = *(const float4*)(scp);
    const float4 sc1 = *(const float4*)(scp + 4);
    const float4 sh0 = *(const float4*)(shp);
    const float4 sh1 = *(const float4*)(shp + 4);

    float v[8];
    {
        const float2 f0 = __half22float2(hp[0]);
        const float2 f1 = __half22float2(hp[1]);
        const float2 f2 = __half22float2(hp[2]);
        const float2 f3 = __half22float2(hp[3]);
        v[0] = fmaf(f0.x, sc0.x, sh0.x);
        v[1] = fmaf(f0.y, sc0.y, sh0.y);
        v[2] = fmaf(f1.x, sc0.z, sh0.z);
        v[3] = fmaf(f1.y, sc0.w, sh0.w);
        v[4] = fmaf(f2.x, sc1.x, sh1.x);
        v[5] = fmaf(f2.y, sc1.y, sh1.y);
        v[6] = fmaf(f3.x, sc1.z, sh1.z);
        v[7] = fmaf(f3.y, sc1.w, sh1.w);
#pragma unroll
        for (int u = 0; u < 8; u++) v[u] = v[u] >= 0.f ? v[u] : v[u] * NEG_SLOPE;
    }

    const int sp = __ldg(&sidx[node]);
    float* ap = out + (size_t)sp * D2 + cg;
    const float4 c0 = *(const float4*)ap;
    const float4 c1 = *(const float4*)(ap + 4);
    const float cur[8] = {c0.x, c0.y, c0.z, c0.w, c1.x, c1.y, c1.z, c1.w};
#pragma unroll
    for (int u = 0; u < 8; u++) {
        if (v[u] > cur[u]) {
            if (v[u] >= 0.f) atomicMax((int*)(ap + u), __float_as_int(v[u]));
            else             atomicMin((unsigned int*)(ap + u), __float_as_uint(v[u]));
        }
    }
}

// ---------------- k6: -inf -> 0 ---------------------------------------------
__global__ void k6(float* __restrict__ out, int out_n) {
    const int i = blockIdx.x * blockDim.x + threadIdx.x;
    if (i < out_n) {
        if (__float_as_uint(out[i]) == 0xFF800000u) out[i] = 0.f;
    }
}

// ---------------- launcher ---------------------------------------------------
extern "C" void kernel_launch(void* const* d_in, const int* in_sizes, int n_in,
                              void* d_out, int out_size)
{
    const float* x     = (const float*)d_in[0];
    const float* W1    = (const float*)d_in[1];
    const float* b1    = (const float*)d_in[2];
    const float* g1    = (const float*)d_in[3];
    const float* beta1 = (const float*)d_in[4];
    const float* W2    = (const float*)d_in[5];
    const float* b2    = (const float*)d_in[6];
    const float* g2    = (const float*)d_in[7];
    const float* beta2 = (const float*)d_in[8];
    const int*   nidx  = (const int*)d_in[9];
    const int*   sidx  = (const int*)d_in[10];
    float* out = (float*)d_out;

    const int n = in_sizes[0] / D0;
    const int smem_k3 = (A3_WORDS + B3_WORDS + SRG * D2 * 2 + D2) * 4 + MBLK * 4;
    const int smem_k1 = (A1_WORDS + B1_WORDS + D1) * 4;
    static int attr_set = 0;
    if (!attr_set) {
        cudaFuncSetAttribute(k3, cudaFuncAttributeMaxDynamicSharedMemorySize, smem_k3);
        cudaFuncSetAttribute(k1m, cudaFuncAttributeMaxDynamicSharedMemorySize, smem_k1);
        attr_set = 1;
    }

    k_init<<<(out_size + 255) / 256, 256>>>(out, out_size);
    k_w2p<<<(D1 * D2 + 255) / 256, 256>>>(W2);
    k_w1p<<<(D1 * D0 + 255) / 256, 256>>>(W1);
    k1m<<<(n + M1BLK - 1) / M1BLK, 256, smem_k1>>>(x, b1, n);
    k_stats1<<<256, 256>>>(nidx, n);
    k_fin1<<<1, 1024>>>(nidx, n, g1, beta1);
    k3<<<(n + MBLK - 1) / MBLK, 256, smem_k3>>>(b2, nidx, n);
    k_fin2<<<1, 1024>>>(g2, beta2);
    k5<<<(n * 8 + 255) / 256, 256>>>(nidx, sidx, out, n);
    k6<<<(out_size + 255) / 256, 256>>>(out, out_size);
}

// round 15
// speedup vs baseline: 1.1463x; 1.0567x over previous
#include <cuda_runtime.h>
#include <cuda_fp16.h>
#include <cstdint>
#include <cstddef>

#define D0 32
#define D1 128
#define D2 64
#define NG 16
#define NEG_SLOPE 0.01f
#define EPSV 1e-5f
#define MAXN 1000000

// ---------------- scratch ----------------------------------------------------
__device__ __half g_h1h[(size_t)MAXN * D1];  // 256 MB fp16 pre-norm layer-1
__device__ __half g_h2h[(size_t)MAXN * D2];  // 128 MB fp16 pre-norm layer-2
__device__ __half g_w2ph[64 * 64 * 2];       // fp16 fragment-permuted W2 (16 KB)
__device__ float g_w1p[4 * 16 * 32 * 2];     // fragment-permuted tf32 W1
__device__ float g_sum1[NG * D1], g_sq1[NG * D1];
__device__ float g_sum2[NG * D2], g_sq2[NG * D2];
__device__ float g_scale1[NG * D1], g_shift1[NG * D1];
__device__ float g_scale2[NG * D2], g_shift2[NG * D2];
__device__ float g_cntf[NG];

__device__ __forceinline__ uint32_t f2tf32(float v) {
    uint32_t u;
    asm("cvt.rna.tf32.f32 %0, %1;" : "=r"(u) : "f"(v));
    return u;
}

// ---------------- init -------------------------------------------------------
__global__ void k_init(float* __restrict__ out, int out_n) {
    int i = blockIdx.x * blockDim.x + threadIdx.x;
    if (i < out_n) out[i] = __int_as_float(0xFF800000);
    if (i < NG * D1) { g_sum1[i] = 0.f; g_sq1[i] = 0.f; }
    if (i < NG * D2) { g_sum2[i] = 0.f; g_sq2[i] = 0.f; }
}

// ---------------- W2 -> fp16 m16n8k16 B-fragment layout ---------------------
__global__ void k_w2p(const float* __restrict__ W2) {
    const int i = blockIdx.x * blockDim.x + threadIdx.x;
    if (i >= D2 * D1) return;
    const int c = i >> 7;
    const int k = i & 127;
    const int kt = k >> 4;
    const int j = c >> 3;
    const int lane = ((c & 7) << 2) + ((k & 7) >> 1);
    const int reg = (k & 15) >> 3;
    const int off = (((kt * 8 + j) * 64 + lane * 2 + reg) << 1) + (k & 1);
    g_w2ph[off] = __float2half(W2[c * D1 + k]);
}

// ---------------- W1 -> tf32 m16n8k8 B-fragment layout ----------------------
__global__ void k_w1p(const float* __restrict__ W1) {
    const int i = blockIdx.x * blockDim.x + threadIdx.x;
    if (i >= D1 * D0) return;
    const int c = i >> 5;
    const int k = i & 31;
    const int kt = k >> 3, krow = k & 7;
    const int j = c >> 3, ncol = c & 7;
    const int off = ((kt * 16 + j) * 32 + ncol * 4 + (krow & 3)) * 2 + (krow >> 2);
    g_w1p[off] = __uint_as_float(f2tf32(W1[c * D0 + k]));
}

// ---------------- k1m: pure tf32 mma GEMM1 -> fp16 h1 -----------------------
#define M1BLK 64
#define FRS 132
#define A1_WORDS (16 * FRS)
#define B1_WORDS 4096

__global__ void __launch_bounds__(256) k1m(
    const float* __restrict__ x, const float* __restrict__ b1, int n)
{
    extern __shared__ float sm[];
    float* aperm = sm;
    float* bperm = aperm + A1_WORDS;
    float* b1s   = bperm + B1_WORDS;     // 128 floats

    const int t = threadIdx.x;
    const int base = blockIdx.x * M1BLK;
    const int cnt = min(M1BLK, n - base);
    const int w = t >> 5;
    const int lane = t & 31;

    {
        const float4* src = (const float4*)g_w1p;
        float4* dst = (float4*)bperm;
        for (int i = t; i < B1_WORDS / 4; i += 256) dst[i] = src[i];
        if (t < D1) b1s[t] = b1[t];
    }
    for (int i = t; i < M1BLK * 8; i += 256) {
        const int node = i >> 3;
        const int kq = (i & 7) << 2;
        float4 v;
        if (node < cnt) v = *(const float4*)(x + (size_t)(base + node) * D0 + kq);
        else { v.x = v.y = v.z = v.w = 0.f; }
        const int mt = node >> 4;
        const int kt = kq >> 3;
        const int rl = node & 15;
        const int regb = (rl >> 3) + (((kq & 7) >> 2) << 1);
        const int laneb = (rl & 7) << 2;
        float* fb = aperm + (mt * 4 + kt) * FRS;
        fb[(laneb + 0) * 4 + regb] = __uint_as_float(f2tf32(v.x));
        fb[(laneb + 1) * 4 + regb] = __uint_as_float(f2tf32(v.y));
        fb[(laneb + 2) * 4 + regb] = __uint_as_float(f2tf32(v.z));
        fb[(laneb + 3) * 4 + regb] = __uint_as_float(f2tf32(v.w));
    }
    __syncthreads();

    const int mt = w >> 1;
    const int nh = w & 1;

    float acc[8][4];
#pragma unroll
    for (int j = 0; j < 8; j++)
#pragma unroll
        for (int r = 0; r < 4; r++) acc[j][r] = 0.f;

#pragma unroll
    for (int kt = 0; kt < 4; kt++) {
        const float4 af = *(const float4*)(aperm + (mt * 4 + kt) * FRS + lane * 4);
        const uint32_t a0 = __float_as_uint(af.x), a1 = __float_as_uint(af.y);
        const uint32_t a2 = __float_as_uint(af.z), a3 = __float_as_uint(af.w);
#pragma unroll
        for (int j = 0; j < 8; j++) {
            const int jg = nh * 8 + j;
            const float2 bf = *(const float2*)(bperm + ((kt * 16 + jg) * 32 + lane) * 2);
            const uint32_t b0 = __float_as_uint(bf.x), b1r = __float_as_uint(bf.y);
            asm volatile(
                "mma.sync.aligned.m16n8k8.row.col.f32.tf32.tf32.f32 "
                "{%0,%1,%2,%3}, {%4,%5,%6,%7}, {%8,%9}, {%0,%1,%2,%3};"
                : "+f"(acc[j][0]), "+f"(acc[j][1]), "+f"(acc[j][2]), "+f"(acc[j][3])
                : "r"(a0), "r"(a1), "r"(a2), "r"(a3), "r"(b0), "r"(b1r));
        }
    }

    const int grp = lane >> 2, tig = lane & 3;
    const int l0 = mt * 16 + grp;
    const int l1 = l0 + 8;
#pragma unroll
    for (int j = 0; j < 8; j++) {
        const int nn = nh * 64 + j * 8 + tig * 2;
        const float bx = b1s[nn], by = b1s[nn + 1];
        const __half2 p0 = __floats2half2_rn(acc[j][0] + bx, acc[j][1] + by);
        const __half2 p1 = __floats2half2_rn(acc[j][2] + bx, acc[j][3] + by);
        if (l0 < cnt) *(__half2*)(g_h1h + (size_t)(base + l0) * D1 + nn) = p0;
        if (l1 < cnt) *(__half2*)(g_h1h + (size_t)(base + l1) * D1 + nn) = p1;
    }
}

// ---------------- k_stats1: vectorized per-graph sums from fp16 h1 ----------
__global__ void __launch_bounds__(256) k_stats1(const int* __restrict__ nidx, int n) {
    const int t = threadIdx.x;
    const int cg = (t & 15) << 3;
    const int nr = t >> 4;
    const int chunk = (n + gridDim.x - 1) / gridDim.x;
    const int start = blockIdx.x * chunk;
    const int end = min(start + chunk, n);

    float s[8], q[8];
#pragma unroll
    for (int u = 0; u < 8; u++) { s[u] = 0.f; q[u] = 0.f; }
    int curg = -1;

    for (int node = start + nr; node < end; node += 16) {
        const int g = __ldg(&nidx[node]);
        if (g != curg) {
            if (curg >= 0) {
#pragma unroll
                for (int u = 0; u < 8; u++) {
                    atomicAdd(&g_sum1[curg * D1 + cg + u], s[u]);
                    atomicAdd(&g_sq1[curg * D1 + cg + u], q[u]);
                    s[u] = 0.f; q[u] = 0.f;
                }
            }
            curg = g;
        }
        const float4 hv = *(const float4*)(g_h1h + (size_t)node * D1 + cg);
        const __half2* hp = (const __half2*)&hv;
#pragma unroll
        for (int p = 0; p < 4; p++) {
            const float2 f = __half22float2(hp[p]);
            s[2 * p + 0] += f.x; q[2 * p + 0] = fmaf(f.x, f.x, q[2 * p + 0]);
            s[2 * p + 1] += f.y; q[2 * p + 1] = fmaf(f.y, f.y, q[2 * p + 1]);
        }
    }
    if (curg >= 0) {
#pragma unroll
        for (int u = 0; u < 8; u++) {
            atomicAdd(&g_sum1[curg * D1 + cg + u], s[u]);
            atomicAdd(&g_sq1[curg * D1 + cg + u], q[u]);
        }
    }
}

// ---------------- finalize layer-1 norm -------------------------------------
__global__ void k_fin1(const int* __restrict__ nidx, int n,
                       const float* __restrict__ gamma, const float* __restrict__ beta)
{
    __shared__ int lb[NG + 1];
    const int t = threadIdx.x;
    if (t <= NG) {
        int lo = 0, hi = n;
        while (lo < hi) { int mid = (lo + hi) >> 1; if (nidx[mid] < t) lo = mid + 1; else hi = mid; }
        lb[t] = lo;
    }
    __syncthreads();
    if (t < NG) g_cntf[t] = (float)max(lb[t + 1] - lb[t], 1);
    for (int idx = t; idx < NG * D1; idx += blockDim.x) {
        const int g = idx >> 7, c = idx & 127;
        const float cf = (float)max(lb[g + 1] - lb[g], 1);
        const float mean = g_sum1[idx] / cf;
        const float var = fmaxf(g_sq1[idx] / cf - mean * mean, 0.f);
        const float sc = gamma[c] * rsqrtf(var + EPSV);
        g_scale1[idx] = sc;
        g_shift1[idx] = fmaf(-mean, sc, beta[c]);
    }
}

// ---------------- k3 fp16 mma: norm1+leaky -> f16 GEMM2 + fused stats2 ------
#define MBLK 128
#define SRG 4
#define A3_WORDS (64 * FRS)
#define B3_WORDS 4096

__global__ void __launch_bounds__(256) k3(
    const float* __restrict__ b2, const int* __restrict__ nidx, int n)
{
    extern __shared__ float sm[];
    float* aperm = sm;
    float* bperm = aperm + A3_WORDS;
    float* sred  = bperm + B3_WORDS;
    float* b2s   = sred + SRG * D2 * 2;
    int*   gs    = (int*)(b2s + D2);

    const int t = threadIdx.x;
    const int base = blockIdx.x * MBLK;
    const int cnt = min(MBLK, n - base);
    const int w = t >> 5;
    const int lane = t & 31;

    {   // stage fp16 B frags + bias
        const float4* src = (const float4*)g_w2ph;
        float4* dst = (float4*)bperm;
        for (int i = t; i < B3_WORDS / 4; i += 256) dst[i] = src[i];
        if (t < D2) b2s[t] = b2[t];
    }
    for (int i = t; i < SRG * D2 * 2; i += 256) sred[i] = 0.f;
    for (int i = t; i < MBLK; i += 256) gs[i] = (i < cnt) ? nidx[base + i] : nidx[base + cnt - 1];
    __syncthreads();
    const int gmin = gs[0];

    // stage A: normalize+leaky h1 -> half2 fragment layout, full K=128
    for (int i = t; i < MBLK * 16; i += 256) {
        const int node = i >> 4;
        const int kq = (i & 15) << 3;
        float vv[8];
        if (node < cnt) {
            const float4 hv = *(const float4*)(g_h1h + (size_t)(base + node) * D1 + kq);
            const __half2* hp = (const __half2*)&hv;
            const int g = gs[node];
            const float* scp = g_scale1 + g * D1 + kq;
            const float* shp = g_shift1 + g * D1 + kq;
            const float4 sc0 = *(const float4*)(scp);
            const float4 sc1 = *(const float4*)(scp + 4);
            const float4 sh0 = *(const float4*)(shp);
            const float4 sh1 = *(const float4*)(shp + 4);
            float2 f0 = __half22float2(hp[0]);
            float2 f1 = __half22float2(hp[1]);
            float2 f2 = __half22float2(hp[2]);
            float2 f3 = __half22float2(hp[3]);
            vv[0] = fmaf(f0.x, sc0.x, sh0.x);
            vv[1] = fmaf(f0.y, sc0.y, sh0.y);
            vv[2] = fmaf(f1.x, sc0.z, sh0.z);
            vv[3] = fmaf(f1.y, sc0.w, sh0.w);
            vv[4] = fmaf(f2.x, sc1.x, sh1.x);
            vv[5] = fmaf(f2.y, sc1.y, sh1.y);
            vv[6] = fmaf(f3.x, sc1.z, sh1.z);
            vv[7] = fmaf(f3.y, sc1.w, sh1.w);
#pragma unroll
            for (int u = 0; u < 8; u++) vv[u] = vv[u] >= 0.f ? vv[u] : vv[u] * NEG_SLOPE;
        } else {
#pragma unroll
            for (int u = 0; u < 8; u++) vv[u] = 0.f;
        }
        const int mt = node >> 4;
        const int kt = kq >> 4;
        const int rl = node & 15;
        const int reg = (rl >> 3) + (((kq & 15) >> 3) << 1);
        float* fb = aperm + (mt * 8 + kt) * FRS;
        const int lb0 = (rl & 7) << 2;
#pragma unroll
        for (int p = 0; p < 4; p++) {
            const __half2 hv2 = __floats2half2_rn(vv[2 * p], vv[2 * p + 1]);
            fb[(lb0 + p) * 4 + reg] = __uint_as_float(*(const uint32_t*)&hv2);
        }
    }
    __syncthreads();

    float acc[8][4];
#pragma unroll
    for (int j = 0; j < 8; j++)
#pragma unroll
        for (int r = 0; r < 4; r++) acc[j][r] = 0.f;

#pragma unroll
    for (int kt = 0; kt < 8; kt++) {
        const float4 af = *(const float4*)(aperm + (w * 8 + kt) * FRS + lane * 4);
        const uint32_t a0 = __float_as_uint(af.x), a1 = __float_as_uint(af.y);
        const uint32_t a2 = __float_as_uint(af.z), a3 = __float_as_uint(af.w);
#pragma unroll
        for (int j = 0; j < 8; j++) {
            const float2 bf = *(const float2*)(bperm + ((kt * 8 + j) * 64 + lane * 2));
            const uint32_t b0 = __float_as_uint(bf.x), b1r = __float_as_uint(bf.y);
            asm volatile(
                "mma.sync.aligned.m16n8k16.row.col.f32.f16.f16.f32 "
                "{%0,%1,%2,%3}, {%4,%5,%6,%7}, {%8,%9}, {%0,%1,%2,%3};"
                : "+f"(acc[j][0]), "+f"(acc[j][1]), "+f"(acc[j][2]), "+f"(acc[j][3])
                : "r"(a0), "r"(a1), "r"(a2), "r"(a3), "r"(b0), "r"(b1r));
        }
    }

    // epilogue: bias, fp16 h2 store, fused stats on rounded values
    const int grp = lane >> 2, tig = lane & 3;
    const int l0 = w * 16 + grp;
    const int l1 = l0 + 8;
    const bool uniform = (w * 16 + 15 < cnt) && (gs[w * 16] == gs[w * 16 + 15]);

#pragma unroll
    for (int j = 0; j < 8; j++) {
        const int nn = j * 8 + tig * 2;
        const float bx = b2s[nn], by = b2s[nn + 1];
        const __half2 p0 = __floats2half2_rn(acc[j][0] + bx, acc[j][1] + by);
        const __half2 p1 = __floats2half2_rn(acc[j][2] + bx, acc[j][3] + by);
        const float2 r0 = __half22float2(p0);
        const float2 r1 = __half22float2(p1);
        if (l0 < cnt) *(__half2*)(g_h2h + (size_t)(base + l0) * D2 + nn) = p0;
        if (l1 < cnt) *(__half2*)(g_h2h + (size_t)(base + l1) * D2 + nn) = p1;

        if (uniform) {
            float s0 = r0.x + r1.x, s1 = r0.y + r1.y;
            float q0 = r0.x * r0.x + r1.x * r1.x, q1 = r0.y * r0.y + r1.y * r1.y;
#pragma unroll
            for (int off = 4; off < 32; off <<= 1) {
                s0 += __shfl_xor_sync(0xffffffffu, s0, off);
                s1 += __shfl_xor_sync(0xffffffffu, s1, off);
                q0 += __shfl_xor_sync(0xffffffffu, q0, off);
                q1 += __shfl_xor_sync(0xffffffffu, q1, off);
            }
            if (lane < 4) {
                const int gl = gs[w * 16] - gmin;
                atomicAdd(&sred[(gl * D2 + nn) * 2 + 0], s0);
                atomicAdd(&sred[(gl * D2 + nn) * 2 + 1], q0);
                atomicAdd(&sred[(gl * D2 + nn + 1) * 2 + 0], s1);
                atomicAdd(&sred[(gl * D2 + nn + 1) * 2 + 1], q1);
            }
        } else {
            if (l0 < cnt) {
                const int gl = gs[l0] - gmin;
                if (gl < SRG) {
                    atomicAdd(&sred[(gl * D2 + nn) * 2 + 0], r0.x);
                    atomicAdd(&sred[(gl * D2 + nn) * 2 + 1], r0.x * r0.x);
                    atomicAdd(&sred[(gl * D2 + nn + 1) * 2 + 0], r0.y);
                    atomicAdd(&sred[(gl * D2 + nn + 1) * 2 + 1], r0.y * r0.y);
                } else {
                    const int g = gs[l0];
                    atomicAdd(&g_sum2[g * D2 + nn], r0.x);
                    atomicAdd(&g_sq2[g * D2 + nn], r0.x * r0.x);
                    atomicAdd(&g_sum2[g * D2 + nn + 1], r0.y);
                    atomicAdd(&g_sq2[g * D2 + nn + 1], r0.y * r0.y);
                }
            }
            if (l1 < cnt) {
                const int gl = gs[l1] - gmin;
                if (gl < SRG) {
                    atomicAdd(&sred[(gl * D2 + nn) * 2 + 0], r1.x);
                    atomicAdd(&sred[(gl * D2 + nn) * 2 + 1], r1.x * r1.x);
                    atomicAdd(&sred[(gl * D2 + nn + 1) * 2 + 0], r1.y);
                    atomicAdd(&sred[(gl * D2 + nn + 1) * 2 + 1], r1.y * r1.y);
                } else {
                    const int g = gs[l1];
                    atomicAdd(&g_sum2[g * D2 + nn], r1.x);
                    atomicAdd(&g_sq2[g * D2 + nn], r1.x * r1.x);
                    atomicAdd(&g_sum2[g * D2 + nn + 1], r1.y);
                    atomicAdd(&g_sq2[g * D2 + nn + 1], r1.y * r1.y);
                }
            }
        }
    }
    __syncthreads();

    const int span = min(gs[cnt - 1] - gmin + 1, SRG);
    for (int ii = t; ii < span * D2; ii += 256) {
        const int gl = ii / D2;
        const int c = ii % D2;
        const float sv = sred[(gl * D2 + c) * 2 + 0];
        const float qv = sred[(gl * D2 + c) * 2 + 1];
        if (sv != 0.f || qv != 0.f) {
            atomicAdd(&g_sum2[(gmin + gl) * D2 + c], sv);
            atomicAdd(&g_sq2[(gmin + gl) * D2 + c], qv);
        }
    }
}

// ---------------- finalize layer-2 norm -------------------------------------
__global__ void k_fin2(const float* __restrict__ gamma, const float* __restrict__ beta) {
    const int t = threadIdx.x;
    for (int idx = t; idx < NG * D2; idx += blockDim.x) {
        const int g = idx >> 6, c = idx & 63;
        const float cf = g_cntf[g];
        const float mean = g_sum2[idx] / cf;
        const float var = fmaxf(g_sq2[idx] / cf - mean * mean, 0.f);
        const float sc = gamma[c] * rsqrtf(var + EPSV);
        g_scale2[idx] = sc;
        g_shift2[idx] = fmaf(-mean, sc, beta[c]);
    }
}

// ---------------- k5: 8 ch/thread, vectorized -------------------------------
__global__ void __launch_bounds__(256) k5(
    const int* __restrict__ nidx, const int* __restrict__ sidx,
    float* __restrict__ out, int n)
{
    const int idx = blockIdx.x * blockDim.x + threadIdx.x;
    if (idx >= n * 8) return;
    const int node = idx >> 3;
    const int cg = (idx & 7) << 3;
    const int g = __ldg(&nidx[node]);

    const float4 hv = *(const float4*)(g_h2h + (size_t)node * D2 + cg);
    const __half2* hp = (const __half2*)&hv;
    const float* scp = g_scale2 + g * D2 + cg;
    const float* shp = g_shift2 + g * D2 + cg;
    const float4 sc0 = *(const float4*)(scp);
    const float4 sc1 = *(const float4*)(scp + 4);
    const float4 sh0 = *(const float4*)(shp);
    const float4 sh1 = *(const float4*)(shp + 4);

    float v[8];
    {
        const float2 f0 = __half22float2(hp[0]);
        const float2 f1 = __half22float2(hp[1]);
        const float2 f2 = __half22float2(hp[2]);
        const float2 f3 = __half22float2(hp[3]);
        v[0] = fmaf(f0.x, sc0.x, sh0.x);
        v[1] = fmaf(f0.y, sc0.y, sh0.y);
        v[2] = fmaf(f1.x, sc0.z, sh0.z);
        v[3] = fmaf(f1.y, sc0.w, sh0.w);
        v[4] = fmaf(f2.x, sc1.x, sh1.x);
        v[5] = fmaf(f2.y, sc1.y, sh1.y);
        v[6] = fmaf(f3.x, sc1.z, sh1.z);
        v[7] = fmaf(f3.y, sc1.w, sh1.w);
#pragma unroll
        for (int u = 0; u < 8; u++) v[u] = v[u] >= 0.f ? v[u] : v[u] * NEG_SLOPE;
    }

    const int sp = __ldg(&sidx[node]);
    float* ap = out + (size_t)sp * D2 + cg;
    const float4 c0 = *(const float4*)ap;
    const float4 c1 = *(const float4*)(ap + 4);
    const float cur[8] = {c0.x, c0.y, c0.z, c0.w, c1.x, c1.y, c1.z, c1.w};
#pragma unroll
    for (int u = 0; u < 8; u++) {
        if (v[u] > cur[u]) {
            if (v[u] >= 0.f) atomicMax((int*)(ap + u), __float_as_int(v[u]));
            else             atomicMin((unsigned int*)(ap + u), __float_as_uint(v[u]));
        }
    }
}

// ---------------- k6: -inf -> 0 ---------------------------------------------
__global__ void k6(float* __restrict__ out, int out_n) {
    const int i = blockIdx.x * blockDim.x + threadIdx.x;
    if (i < out_n) {
        if (__float_as_uint(out[i]) == 0xFF800000u) out[i] = 0.f;
    }
}

// ---------------- launcher ---------------------------------------------------
extern "C" void kernel_launch(void* const* d_in, const int* in_sizes, int n_in,
                              void* d_out, int out_size)
{
    const float* x     = (const float*)d_in[0];
    const float* W1    = (const float*)d_in[1];
    const float* b1    = (const float*)d_in[2];
    const float* g1    = (const float*)d_in[3];
    const float* beta1 = (const float*)d_in[4];
    const float* W2    = (const float*)d_in[5];
    const float* b2    = (const float*)d_in[6];
    const float* g2    = (const float*)d_in[7];
    const float* beta2 = (const float*)d_in[8];
    const int*   nidx  = (const int*)d_in[9];
    const int*   sidx  = (const int*)d_in[10];
    float* out = (float*)d_out;

    const int n = in_sizes[0] / D0;
    const int smem_k3 = (A3_WORDS + B3_WORDS + SRG * D2 * 2 + D2) * 4 + MBLK * 4;
    const int smem_k1 = (A1_WORDS + B1_WORDS + D1) * 4;
    static int attr_set = 0;
    if (!attr_set) {
        cudaFuncSetAttribute(k3, cudaFuncAttributeMaxDynamicSharedMemorySize, smem_k3);
        cudaFuncSetAttribute(k1m, cudaFuncAttributeMaxDynamicSharedMemorySize, smem_k1);
        attr_set = 1;
    }

    k_init<<<(out_size + 255) / 256, 256>>>(out, out_size);
    k_w2p<<<(D1 * D2 + 255) / 256, 256>>>(W2);
    k_w1p<<<(D1 * D0 + 255) / 256, 256>>>(W1);
    k1m<<<(n + M1BLK - 1) / M1BLK, 256, smem_k1>>>(x, b1, n);
    k_stats1<<<512, 256>>>(nidx, n);
    k_fin1<<<1, 1024>>>(nidx, n, g1, beta1);
    k3<<<(n + MBLK - 1) / MBLK, 256, smem_k3>>>(b2, nidx, n);
    k_fin2<<<1, 1024>>>(g2, beta2);
    k5<<<(n * 8 + 255) / 256, 256>>>(nidx, sidx, out, n);
    k6<<<(out_size + 255) / 256, 256>>>(out, out_size);
}

// round 16
// speedup vs baseline: 1.1614x; 1.0132x over previous
#include <cuda_runtime.h>
#include <cuda_fp16.h>
#include <cstdint>
#include <cstddef>

#define D0 32
#define D1 128
#define D2 64
#define NG 16
#define NEG_SLOPE 0.01f
#define EPSV 1e-5f
#define MAXN 1000000

// ---------------- scratch ----------------------------------------------------
__device__ __half g_h1h[(size_t)MAXN * D1];  // 256 MB fp16 pre-norm layer-1
__device__ __half g_h2h[(size_t)MAXN * D2];  // 128 MB fp16 pre-norm layer-2
__device__ __half g_w2ph[64 * 64 * 2];       // fp16 fragment-permuted W2 (16 KB)
__device__ float g_w1p[4 * 16 * 32 * 2];     // fragment-permuted tf32 W1
__device__ float g_sum1[NG * D1], g_sq1[NG * D1];
__device__ float g_sum2[NG * D2], g_sq2[NG * D2];
__device__ float g_scale1[NG * D1], g_shift1[NG * D1];
__device__ float g_scale2[NG * D2], g_shift2[NG * D2];
__device__ float g_cntf[NG];

__device__ __forceinline__ uint32_t f2tf32(float v) {
    uint32_t u;
    asm("cvt.rna.tf32.f32 %0, %1;" : "=r"(u) : "f"(v));
    return u;
}

// ---------------- init -------------------------------------------------------
__global__ void k_init(float* __restrict__ out, int out_n) {
    int i = blockIdx.x * blockDim.x + threadIdx.x;
    if (i < out_n) out[i] = __int_as_float(0xFF800000);
    if (i < NG * D1) { g_sum1[i] = 0.f; g_sq1[i] = 0.f; }
    if (i < NG * D2) { g_sum2[i] = 0.f; g_sq2[i] = 0.f; }
}

// ---------------- W2 -> fp16 m16n8k16 B-fragment layout ---------------------
__global__ void k_w2p(const float* __restrict__ W2) {
    const int i = blockIdx.x * blockDim.x + threadIdx.x;
    if (i >= D2 * D1) return;
    const int c = i >> 7;
    const int k = i & 127;
    const int kt = k >> 4;
    const int j = c >> 3;
    const int lane = ((c & 7) << 2) + ((k & 7) >> 1);
    const int reg = (k & 15) >> 3;
    const int off = (((kt * 8 + j) * 64 + lane * 2 + reg) << 1) + (k & 1);
    g_w2ph[off] = __float2half(W2[c * D1 + k]);
}

// ---------------- W1 -> tf32 m16n8k8 B-fragment layout ----------------------
__global__ void k_w1p(const float* __restrict__ W1) {
    const int i = blockIdx.x * blockDim.x + threadIdx.x;
    if (i >= D1 * D0) return;
    const int c = i >> 5;
    const int k = i & 31;
    const int kt = k >> 3, krow = k & 7;
    const int j = c >> 3, ncol = c & 7;
    const int off = ((kt * 16 + j) * 32 + ncol * 4 + (krow & 3)) * 2 + (krow >> 2);
    g_w1p[off] = __uint_as_float(f2tf32(W1[c * D0 + k]));
}

// ---------------- k1m: tf32 mma GEMM1 -> fp16 h1 + fused stats1 -------------
#define M1BLK 64
#define FRS 132
#define SRG 4
#define A1_WORDS (16 * FRS)
#define B1_WORDS 4096

__global__ void __launch_bounds__(256) k1m(
    const float* __restrict__ x, const float* __restrict__ b1,
    const int* __restrict__ nidx, int n)
{
    extern __shared__ float sm[];
    float* aperm = sm;
    float* bperm = aperm + A1_WORDS;
    float* b1s   = bperm + B1_WORDS;            // 128 floats
    float* sred  = b1s + D1;                    // SRG*D1*2 = 1024 floats (4 KB)
    int*   gs    = (int*)(sred + SRG * D1 * 2); // 64 ints

    const int t = threadIdx.x;
    const int base = blockIdx.x * M1BLK;
    const int cnt = min(M1BLK, n - base);
    const int w = t >> 5;
    const int lane = t & 31;

    {
        const float4* src = (const float4*)g_w1p;
        float4* dst = (float4*)bperm;
        for (int i = t; i < B1_WORDS / 4; i += 256) dst[i] = src[i];
        if (t < D1) b1s[t] = b1[t];
    }
    for (int i = t; i < SRG * D1 * 2; i += 256) sred[i] = 0.f;
    for (int i = t; i < M1BLK; i += 256) gs[i] = (i < cnt) ? nidx[base + i] : nidx[base + cnt - 1];

    for (int i = t; i < M1BLK * 8; i += 256) {
        const int node = i >> 3;
        const int kq = (i & 7) << 2;
        float4 v;
        if (node < cnt) v = *(const float4*)(x + (size_t)(base + node) * D0 + kq);
        else { v.x = v.y = v.z = v.w = 0.f; }
        const int mt = node >> 4;
        const int kt = kq >> 3;
        const int rl = node & 15;
        const int regb = (rl >> 3) + (((kq & 7) >> 2) << 1);
        const int laneb = (rl & 7) << 2;
        float* fb = aperm + (mt * 4 + kt) * FRS;
        fb[(laneb + 0) * 4 + regb] = __uint_as_float(f2tf32(v.x));
        fb[(laneb + 1) * 4 + regb] = __uint_as_float(f2tf32(v.y));
        fb[(laneb + 2) * 4 + regb] = __uint_as_float(f2tf32(v.z));
        fb[(laneb + 3) * 4 + regb] = __uint_as_float(f2tf32(v.w));
    }
    __syncthreads();
    const int gmin = gs[0];

    const int mt = w >> 1;
    const int nh = w & 1;

    float acc[8][4];
#pragma unroll
    for (int j = 0; j < 8; j++)
#pragma unroll
        for (int r = 0; r < 4; r++) acc[j][r] = 0.f;

#pragma unroll
    for (int kt = 0; kt < 4; kt++) {
        const float4 af = *(const float4*)(aperm + (mt * 4 + kt) * FRS + lane * 4);
        const uint32_t a0 = __float_as_uint(af.x), a1 = __float_as_uint(af.y);
        const uint32_t a2 = __float_as_uint(af.z), a3 = __float_as_uint(af.w);
#pragma unroll
        for (int j = 0; j < 8; j++) {
            const int jg = nh * 8 + j;
            const float2 bf = *(const float2*)(bperm + ((kt * 16 + jg) * 32 + lane) * 2);
            const uint32_t b0 = __float_as_uint(bf.x), b1r = __float_as_uint(bf.y);
            asm volatile(
                "mma.sync.aligned.m16n8k8.row.col.f32.tf32.tf32.f32 "
                "{%0,%1,%2,%3}, {%4,%5,%6,%7}, {%8,%9}, {%0,%1,%2,%3};"
                : "+f"(acc[j][0]), "+f"(acc[j][1]), "+f"(acc[j][2]), "+f"(acc[j][3])
                : "r"(a0), "r"(a1), "r"(a2), "r"(a3), "r"(b0), "r"(b1r));
        }
    }

    // epilogue: bias, fp16 h1 store, fused stats (k3-style)
    const int grp = lane >> 2, tig = lane & 3;
    const int l0 = mt * 16 + grp;
    const int l1 = l0 + 8;
    const bool uniform = (mt * 16 + 15 < cnt) && (gs[mt * 16] == gs[mt * 16 + 15]);

#pragma unroll
    for (int j = 0; j < 8; j++) {
        const int nn = nh * 64 + j * 8 + tig * 2;
        const float bx = b1s[nn], by = b1s[nn + 1];
        const __half2 p0 = __floats2half2_rn(acc[j][0] + bx, acc[j][1] + by);
        const __half2 p1 = __floats2half2_rn(acc[j][2] + bx, acc[j][3] + by);
        const float2 r0 = __half22float2(p0);
        const float2 r1 = __half22float2(p1);
        if (l0 < cnt) *(__half2*)(g_h1h + (size_t)(base + l0) * D1 + nn) = p0;
        if (l1 < cnt) *(__half2*)(g_h1h + (size_t)(base + l1) * D1 + nn) = p1;

        if (uniform) {
            float s0 = r0.x + r1.x, s1 = r0.y + r1.y;
            float q0 = r0.x * r0.x + r1.x * r1.x, q1 = r0.y * r0.y + r1.y * r1.y;
#pragma unroll
            for (int off = 4; off < 32; off <<= 1) {
                s0 += __shfl_xor_sync(0xffffffffu, s0, off);
                s1 += __shfl_xor_sync(0xffffffffu, s1, off);
                q0 += __shfl_xor_sync(0xffffffffu, q0, off);
                q1 += __shfl_xor_sync(0xffffffffu, q1, off);
            }
            if (lane < 4) {
                const int gl = gs[mt * 16] - gmin;
                atomicAdd(&sred[(gl * D1 + nn) * 2 + 0], s0);
                atomicAdd(&sred[(gl * D1 + nn) * 2 + 1], q0);
                atomicAdd(&sred[(gl * D1 + nn + 1) * 2 + 0], s1);
                atomicAdd(&sred[(gl * D1 + nn + 1) * 2 + 1], q1);
            }
        } else {
            if (l0 < cnt) {
                const int gl = gs[l0] - gmin;
                if (gl < SRG) {
                    atomicAdd(&sred[(gl * D1 + nn) * 2 + 0], r0.x);
                    atomicAdd(&sred[(gl * D1 + nn) * 2 + 1], r0.x * r0.x);
                    atomicAdd(&sred[(gl * D1 + nn + 1) * 2 + 0], r0.y);
                    atomicAdd(&sred[(gl * D1 + nn + 1) * 2 + 1], r0.y * r0.y);
                } else {
                    const int g = gs[l0];
                    atomicAdd(&g_sum1[g * D1 + nn], r0.x);
                    atomicAdd(&g_sq1[g * D1 + nn], r0.x * r0.x);
                    atomicAdd(&g_sum1[g * D1 + nn + 1], r0.y);
                    atomicAdd(&g_sq1[g * D1 + nn + 1], r0.y * r0.y);
                }
            }
            if (l1 < cnt) {
                const int gl = gs[l1] - gmin;
                if (gl < SRG) {
                    atomicAdd(&sred[(gl * D1 + nn) * 2 + 0], r1.x);
                    atomicAdd(&sred[(gl * D1 + nn) * 2 + 1], r1.x * r1.x);
                    atomicAdd(&sred[(gl * D1 + nn + 1) * 2 + 0], r1.y);
                    atomicAdd(&sred[(gl * D1 + nn + 1) * 2 + 1], r1.y * r1.y);
                } else {
                    const int g = gs[l1];
                    atomicAdd(&g_sum1[g * D1 + nn], r1.x);
                    atomicAdd(&g_sq1[g * D1 + nn], r1.x * r1.x);
                    atomicAdd(&g_sum1[g * D1 + nn + 1], r1.y);
                    atomicAdd(&g_sq1[g * D1 + nn + 1], r1.y * r1.y);
                }
            }
        }
    }
    __syncthreads();

    const int span = min(gs[cnt - 1] - gmin + 1, SRG);
    for (int ii = t; ii < span * D1; ii += 256) {
        const int gl = ii / D1;
        const int c = ii % D1;
        const float sv = sred[(gl * D1 + c) * 2 + 0];
        const float qv = sred[(gl * D1 + c) * 2 + 1];
        if (sv != 0.f || qv != 0.f) {
            atomicAdd(&g_sum1[(gmin + gl) * D1 + c], sv);
            atomicAdd(&g_sq1[(gmin + gl) * D1 + c], qv);
        }
    }
}

// ---------------- finalize layer-1 norm -------------------------------------
__global__ void k_fin1(const int* __restrict__ nidx, int n,
                       const float* __restrict__ gamma, const float* __restrict__ beta)
{
    __shared__ int lb[NG + 1];
    const int t = threadIdx.x;
    if (t <= NG) {
        int lo = 0, hi = n;
        while (lo < hi) { int mid = (lo + hi) >> 1; if (nidx[mid] < t) lo = mid + 1; else hi = mid; }
        lb[t] = lo;
    }
    __syncthreads();
    if (t < NG) g_cntf[t] = (float)max(lb[t + 1] - lb[t], 1);
    for (int idx = t; idx < NG * D1; idx += blockDim.x) {
        const int g = idx >> 7, c = idx & 127;
        const float cf = (float)max(lb[g + 1] - lb[g], 1);
        const float mean = g_sum1[idx] / cf;
        const float var = fmaxf(g_sq1[idx] / cf - mean * mean, 0.f);
        const float sc = gamma[c] * rsqrtf(var + EPSV);
        g_scale1[idx] = sc;
        g_shift1[idx] = fmaf(-mean, sc, beta[c]);
    }
}

// ---------------- k3 fp16 mma: norm1+leaky -> f16 GEMM2 + fused stats2 ------
#define MBLK 128
#define A3_WORDS (64 * FRS)
#define B3_WORDS 4096

__global__ void __launch_bounds__(256) k3(
    const float* __restrict__ b2, const int* __restrict__ nidx, int n)
{
    extern __shared__ float sm[];
    float* aperm = sm;
    float* bperm = aperm + A3_WORDS;
    float* sred  = bperm + B3_WORDS;
    float* b2s   = sred + SRG * D2 * 2;
    int*   gs    = (int*)(b2s + D2);

    const int t = threadIdx.x;
    const int base = blockIdx.x * MBLK;
    const int cnt = min(MBLK, n - base);
    const int w = t >> 5;
    const int lane = t & 31;

    {   // stage fp16 B frags + bias
        const float4* src = (const float4*)g_w2ph;
        float4* dst = (float4*)bperm;
        for (int i = t; i < B3_WORDS / 4; i += 256) dst[i] = src[i];
        if (t < D2) b2s[t] = b2[t];
    }
    for (int i = t; i < SRG * D2 * 2; i += 256) sred[i] = 0.f;
    for (int i = t; i < MBLK; i += 256) gs[i] = (i < cnt) ? nidx[base + i] : nidx[base + cnt - 1];
    __syncthreads();
    const int gmin = gs[0];

    // stage A: normalize+leaky h1 -> half2 fragment layout, full K=128
    for (int i = t; i < MBLK * 16; i += 256) {
        const int node = i >> 4;
        const int kq = (i & 15) << 3;
        float vv[8];
        if (node < cnt) {
            const float4 hv = *(const float4*)(g_h1h + (size_t)(base + node) * D1 + kq);
            const __half2* hp = (const __half2*)&hv;
            const int g = gs[node];
            const float* scp = g_scale1 + g * D1 + kq;
            const float* shp = g_shift1 + g * D1 + kq;
            const float4 sc0 = *(const float4*)(scp);
            const float4 sc1 = *(const float4*)(scp + 4);
            const float4 sh0 = *(const float4*)(shp);
            const float4 sh1 = *(const float4*)(shp + 4);
            float2 f0 = __half22float2(hp[0]);
            float2 f1 = __half22float2(hp[1]);
            float2 f2 = __half22float2(hp[2]);
            float2 f3 = __half22float2(hp[3]);
            vv[0] = fmaf(f0.x, sc0.x, sh0.x);
            vv[1] = fmaf(f0.y, sc0.y, sh0.y);
            vv[2] = fmaf(f1.x, sc0.z, sh0.z);
            vv[3] = fmaf(f1.y, sc0.w, sh0.w);
            vv[4] = fmaf(f2.x, sc1.x, sh1.x);
            vv[5] = fmaf(f2.y, sc1.y, sh1.y);
            vv[6] = fmaf(f3.x, sc1.z, sh1.z);
            vv[7] = fmaf(f3.y, sc1.w, sh1.w);
#pragma unroll
            for (int u = 0; u < 8; u++) vv[u] = vv[u] >= 0.f ? vv[u] : vv[u] * NEG_SLOPE;
        } else {
#pragma unroll
            for (int u = 0; u < 8; u++) vv[u] = 0.f;
        }
        const int mt = node >> 4;
        const int kt = kq >> 4;
        const int rl = node & 15;
        const int reg = (rl >> 3) + (((kq & 15) >> 3) << 1);
        float* fb = aperm + (mt * 8 + kt) * FRS;
        const int lb0 = (rl & 7) << 2;
#pragma unroll
        for (int p = 0; p < 4; p++) {
            const __half2 hv2 = __floats2half2_rn(vv[2 * p], vv[2 * p + 1]);
            fb[(lb0 + p) * 4 + reg] = __uint_as_float(*(const uint32_t*)&hv2);
        }
    }
    __syncthreads();

    float acc[8][4];
#pragma unroll
    for (int j = 0; j < 8; j++)
#pragma unroll
        for (int r = 0; r < 4; r++) acc[j][r] = 0.f;

#pragma unroll
    for (int kt = 0; kt < 8; kt++) {
        const float4 af = *(const float4*)(aperm + (w * 8 + kt) * FRS + lane * 4);
        const uint32_t a0 = __float_as_uint(af.x), a1 = __float_as_uint(af.y);
        const uint32_t a2 = __float_as_uint(af.z), a3 = __float_as_uint(af.w);
#pragma unroll
        for (int j = 0; j < 8; j++) {
            const float2 bf = *(const float2*)(bperm + ((kt * 8 + j) * 64 + lane * 2));
            const uint32_t b0 = __float_as_uint(bf.x), b1r = __float_as_uint(bf.y);
            asm volatile(
                "mma.sync.aligned.m16n8k16.row.col.f32.f16.f16.f32 "
                "{%0,%1,%2,%3}, {%4,%5,%6,%7}, {%8,%9}, {%0,%1,%2,%3};"
                : "+f"(acc[j][0]), "+f"(acc[j][1]), "+f"(acc[j][2]), "+f"(acc[j][3])
                : "r"(a0), "r"(a1), "r"(a2), "r"(a3), "r"(b0), "r"(b1r));
        }
    }

    // epilogue: bias, fp16 h2 store, fused stats on rounded values
    const int grp = lane >> 2, tig = lane & 3;
    const int l0 = w * 16 + grp;
    const int l1 = l0 + 8;
    const bool uniform = (w * 16 + 15 < cnt) && (gs[w * 16] == gs[w * 16 + 15]);

#pragma unroll
    for (int j = 0; j < 8; j++) {
        const int nn = j * 8 + tig * 2;
        const float bx = b2s[nn], by = b2s[nn + 1];
        const __half2 p0 = __floats2half2_rn(acc[j][0] + bx, acc[j][1] + by);
        const __half2 p1 = __floats2half2_rn(acc[j][2] + bx, acc[j][3] + by);
        const float2 r0 = __half22float2(p0);
        const float2 r1 = __half22float2(p1);
        if (l0 < cnt) *(__half2*)(g_h2h + (size_t)(base + l0) * D2 + nn) = p0;
        if (l1 < cnt) *(__half2*)(g_h2h + (size_t)(base + l1) * D2 + nn) = p1;

        if (uniform) {
            float s0 = r0.x + r1.x, s1 = r0.y + r1.y;
            float q0 = r0.x * r0.x + r1.x * r1.x, q1 = r0.y * r0.y + r1.y * r1.y;
#pragma unroll
            for (int off = 4; off < 32; off <<= 1) {
                s0 += __shfl_xor_sync(0xffffffffu, s0, off);
                s1 += __shfl_xor_sync(0xffffffffu, s1, off);
                q0 += __shfl_xor_sync(0xffffffffu, q0, off);
                q1 += __shfl_xor_sync(0xffffffffu, q1, off);
            }
            if (lane < 4) {
                const int gl = gs[w * 16] - gmin;
                atomicAdd(&sred[(gl * D2 + nn) * 2 + 0], s0);
                atomicAdd(&sred[(gl * D2 + nn) * 2 + 1], q0);
                atomicAdd(&sred[(gl * D2 + nn + 1) * 2 + 0], s1);
                atomicAdd(&sred[(gl * D2 + nn + 1) * 2 + 1], q1);
            }
        } else {
            if (l0 < cnt) {
                const int gl = gs[l0] - gmin;
                if (gl < SRG) {
                    atomicAdd(&sred[(gl * D2 + nn) * 2 + 0], r0.x);
                    atomicAdd(&sred[(gl * D2 + nn) * 2 + 1], r0.x * r0.x);
                    atomicAdd(&sred[(gl * D2 + nn + 1) * 2 + 0], r0.y);
                    atomicAdd(&sred[(gl * D2 + nn + 1) * 2 + 1], r0.y * r0.y);
                } else {
                    const int g = gs[l0];
                    atomicAdd(&g_sum2[g * D2 + nn], r0.x);
                    atomicAdd(&g_sq2[g * D2 + nn], r0.x * r0.x);
                    atomicAdd(&g_sum2[g * D2 + nn + 1], r0.y);
                    atomicAdd(&g_sq2[g * D2 + nn + 1], r0.y * r0.y);
                }
            }
            if (l1 < cnt) {
                const int gl = gs[l1] - gmin;
                if (gl < SRG) {
                    atomicAdd(&sred[(gl * D2 + nn) * 2 + 0], r1.x);
                    atomicAdd(&sred[(gl * D2 + nn) * 2 + 1], r1.x * r1.x);
                    atomicAdd(&sred[(gl * D2 + nn + 1) * 2 + 0], r1.y);
                    atomicAdd(&sred[(gl * D2 + nn + 1) * 2 + 1], r1.y * r1.y);
                } else {
                    const int g = gs[l1];
                    atomicAdd(&g_sum2[g * D2 + nn], r1.x);
                    atomicAdd(&g_sq2[g * D2 + nn], r1.x * r1.x);
                    atomicAdd(&g_sum2[g * D2 + nn + 1], r1.y);
                    atomicAdd(&g_sq2[g * D2 + nn + 1], r1.y * r1.y);
                }
            }
        }
    }
    __syncthreads();

    const int span = min(gs[cnt - 1] - gmin + 1, SRG);
    for (int ii = t; ii < span * D2; ii += 256) {
        const int gl = ii / D2;
        const int c = ii % D2;
        const float sv = sred[(gl * D2 + c) * 2 + 0];
        const float qv = sred[(gl * D2 + c) * 2 + 1];
        if (sv != 0.f || qv != 0.f) {
            atomicAdd(&g_sum2[(gmin + gl) * D2 + c], sv);
            atomicAdd(&g_sq2[(gmin + gl) * D2 + c], qv);
        }
    }
}

// ---------------- finalize layer-2 norm -------------------------------------
__global__ void k_fin2(const float* __restrict__ gamma, const float* __restrict__ beta) {
    const int t = threadIdx.x;
    for (int idx = t; idx < NG * D2; idx += blockDim.x) {
        const int g = idx >> 6, c = idx & 63;
        const float cf = g_cntf[g];
        const float mean = g_sum2[idx] / cf;
        const float var = fmaxf(g_sq2[idx] / cf - mean * mean, 0.f);
        const float sc = gamma[c] * rsqrtf(var + EPSV);
        g_scale2[idx] = sc;
        g_shift2[idx] = fmaf(-mean, sc, beta[c]);
    }
}

// ---------------- k5: 8 ch/thread, vectorized -------------------------------
__global__ void __launch_bounds__(256) k5(
    const int* __restrict__ nidx, const int* __restrict__ sidx,
    float* __restrict__ out, int n)
{
    const int idx = blockIdx.x * blockDim.x + threadIdx.x;
    if (idx >= n * 8) return;
    const int node = idx >> 3;
    const int cg = (idx & 7) << 3;
    const int g = __ldg(&nidx[node]);

    const float4 hv = *(const float4*)(g_h2h + (size_t)node * D2 + cg);
    const __half2* hp = (const __half2*)&hv;
    const float* scp = g_scale2 + g * D2 + cg;
    const float* shp = g_shift2 + g * D2 + cg;
    const float4 sc0 = *(const float4*)(scp);
    const float4 sc1 = *(const float4*)(scp + 4);
    const float4 sh0 = *(const float4*)(shp);
    const float4 sh1 = *(const float4*)(shp + 4);

    float v[8];
    {
        const float2 f0 = __half22float2(hp[0]);
        const float2 f1 = __half22float2(hp[1]);
        const float2 f2 = __half22float2(hp[2]);
        const float2 f3 = __half22float2(hp[3]);
        v[0] = fmaf(f0.x, sc0.x, sh0.x);
        v[1] = fmaf(f0.y, sc0.y, sh0.y);
        v[2] = fmaf(f1.x, sc0.z, sh0.z);
        v[3] = fmaf(f1.y, sc0.w, sh0.w);
        v[4] = fmaf(f2.x, sc1.x, sh1.x);
        v[5] = fmaf(f2.y, sc1.y, sh1.y);
        v[6] = fmaf(f3.x, sc1.z, sh1.z);
        v[7] = fmaf(f3.y, sc1.w, sh1.w);
#pragma unroll
        for (int u = 0; u < 8; u++) v[u] = v[u] >= 0.f ? v[u] : v[u] * NEG_SLOPE;
    }

    const int sp = __ldg(&sidx[node]);
    float* ap = out + (size_t)sp * D2 + cg;
    const float4 c0 = *(const float4*)ap;
    const float4 c1 = *(const float4*)(ap + 4);
    const float cur[8] = {c0.x, c0.y, c0.z, c0.w, c1.x, c1.y, c1.z, c1.w};
#pragma unroll
    for (int u = 0; u < 8; u++) {
        if (v[u] > cur[u]) {
            if (v[u] >= 0.f) atomicMax((int*)(ap + u), __float_as_int(v[u]));
            else             atomicMin((unsigned int*)(ap + u), __float_as_uint(v[u]));
        }
    }
}

// ---------------- k6: -inf -> 0 ---------------------------------------------
__global__ void k6(float* __restrict__ out, int out_n) {
    const int i = blockIdx.x * blockDim.x + threadIdx.x;
    if (i < out_n) {
        if (__float_as_uint(out[i]) == 0xFF800000u) out[i] = 0.f;
    }
}

// ---------------- launcher ---------------------------------------------------
extern "C" void kernel_launch(void* const* d_in, const int* in_sizes, int n_in,
                              void* d_out, int out_size)
{
    const float* x     = (const float*)d_in[0];
    const float* W1    = (const float*)d_in[1];
    const float* b1    = (const float*)d_in[2];
    const float* g1    = (const float*)d_in[3];
    const float* beta1 = (const float*)d_in[4];
    const float* W2    = (const float*)d_in[5];
    const float* b2    = (const float*)d_in[6];
    const float* g2    = (const float*)d_in[7];
    const float* beta2 = (const float*)d_in[8];
    const int*   nidx  = (const int*)d_in[9];
    const int*   sidx  = (const int*)d_in[10];
    float* out = (float*)d_out;

    const int n = in_sizes[0] / D0;
    const int smem_k3 = (A3_WORDS + B3_WORDS + SRG * D2 * 2 + D2) * 4 + MBLK * 4;
    const int smem_k1 = (A1_WORDS + B1_WORDS + D1 + SRG * D1 * 2) * 4 + M1BLK * 4;
    static int attr_set = 0;
    if (!attr_set) {
        cudaFuncSetAttribute(k3, cudaFuncAttributeMaxDynamicSharedMemorySize, smem_k3);
        cudaFuncSetAttribute(k1m, cudaFuncAttributeMaxDynamicSharedMemorySize, smem_k1);
        attr_set = 1;
    }

    k_init<<<(out_size + 255) / 256, 256>>>(out, out_size);
    k_w2p<<<(D1 * D2 + 255) / 256, 256>>>(W2);
    k_w1p<<<(D1 * D0 + 255) / 256, 256>>>(W1);
    k1m<<<(n + M1BLK - 1) / M1BLK, 256, smem_k1>>>(x, b1, nidx, n);
    k_fin1<<<1, 1024>>>(nidx, n, g1, beta1);
    k3<<<(n + MBLK - 1) / MBLK, 256, smem_k3>>>(b2, nidx, n);
    k_fin2<<<1, 1024>>>(g2, beta2);
    k5<<<(n * 8 + 255) / 256, 256>>>(nidx, sidx, out, n);
    k6<<<(out_size + 255) / 256, 256>>>(out, out_size);
}